// round 2
// baseline (speedup 1.0000x reference)
#include <cuda_runtime.h>
#include <cuda_bf16.h>
#include <cstdint>
#include <cstddef>

// ---------------------------------------------------------------------------
// Mamba2 block forward, SEQ=4096, D_MODEL=1024.
// Pipeline:
//  K0  : convert u->bf16; split W_in / W_out into bf16 hi+lo
//  K1  : GEMM1  zxbcdt = ub @ W_in^T          (split-B bf16 tensor cores)
//  K2  : causal depthwise conv(4) + SiLU on xBC columns
//  K2b : dt softplus, per-chunk log-decay cumsum
//  K3a : per-chunk local final states  (64x128x128 fp32 GEMM per (c,h))
//  K3b : sequential chunk-state propagation (32 steps, elementwise)
//  K3c : per-chunk outputs: G=C.B^T masked/decayed, Y=G@X + C@h_init + D*x
//  K4  : RMSNorm + silu(z) gate -> yg hi/lo bf16
//  K5  : GEMM2  out = yg @ W_out^T            (split-A and split-B)
// ---------------------------------------------------------------------------

#define SEQ   4096
#define DM    1024
#define DIP   4384
#define DIPP  4480        // padded to multiple of 128
#define DI    2048
#define DCI   2304        // conv channels (x,B,C)
#define NH    32
#define HD    64
#define DS    128
#define CH    128
#define NC    32

// ------------------------------ scratch ------------------------------------
__device__ __nv_bfloat16 g_ub[SEQ * DM];
__device__ __nv_bfloat16 g_Win_hi[DIPP * DM];
__device__ __nv_bfloat16 g_Win_lo[DIPP * DM];
__device__ __nv_bfloat16 g_Wout_hi[DM * DI];
__device__ __nv_bfloat16 g_Wout_lo[DM * DI];
__device__ float g_zx[(size_t)SEQ * DIPP];     // zxbcdt (padded cols)
__device__ float g_xc[(size_t)SEQ * DCI];      // conv(x,B,C) after SiLU
__device__ float g_dts[NC * NH * CH];          // softplus(dt)
__device__ float g_cumS[NC * NH * CH];         // inclusive cumsum of dt*A (log decay)
__device__ float g_Sloc[(size_t)NC * NH * HD * DS];
__device__ float g_hinit[(size_t)NC * NH * HD * DS];
__device__ float g_y[(size_t)SEQ * DI];
__device__ __nv_bfloat16 g_yg_hi[(size_t)SEQ * DI];
__device__ __nv_bfloat16 g_yg_lo[(size_t)SEQ * DI];

// ------------------------------ helpers ------------------------------------
__device__ __forceinline__ void cp16(void* smem, const void* gmem) {
    uint32_t s = (uint32_t)__cvta_generic_to_shared(smem);
    asm volatile("cp.async.cg.shared.global [%0], [%1], 16;\n" :: "r"(s), "l"(gmem));
}
__device__ __forceinline__ void cp_commit() { asm volatile("cp.async.commit_group;\n"); }

__device__ __forceinline__ uint32_t lds32(const __nv_bfloat16* p) {
    return *reinterpret_cast<const uint32_t*>(p);
}

__device__ __forceinline__ void mma16816(float* d, const uint32_t* a, uint32_t b0, uint32_t b1) {
    asm volatile(
        "mma.sync.aligned.m16n8k16.row.col.f32.bf16.bf16.f32 "
        "{%0,%1,%2,%3}, {%4,%5,%6,%7}, {%8,%9}, {%0,%1,%2,%3};\n"
        : "+f"(d[0]), "+f"(d[1]), "+f"(d[2]), "+f"(d[3])
        : "r"(a[0]), "r"(a[1]), "r"(a[2]), "r"(a[3]), "r"(b0), "r"(b1));
}

__device__ __forceinline__ float silu(float x) { return x / (1.f + expf(-x)); }

// ------------------------------ K0 -----------------------------------------
__global__ void k_cvt_u(const float* __restrict__ u) {
    for (int i = blockIdx.x * blockDim.x + threadIdx.x; i < SEQ * DM;
         i += gridDim.x * blockDim.x)
        g_ub[i] = __float2bfloat16(u[i]);
}

__global__ void k_split_win(const float* __restrict__ W) {
    int i = blockIdx.x * blockDim.x + threadIdx.x;
    if (i >= DIPP * DM) return;
    int r = i >> 10;
    int c = i & 1023;
    float w = (r < DIP) ? W[r * DM + c] : 0.f;
    __nv_bfloat16 hi = __float2bfloat16(w);
    g_Win_hi[i] = hi;
    g_Win_lo[i] = __float2bfloat16(w - __bfloat162float(hi));
}

__global__ void k_split_wout(const float* __restrict__ W) {
    int i = blockIdx.x * blockDim.x + threadIdx.x;
    if (i >= DM * DI) return;
    float w = W[i];
    __nv_bfloat16 hi = __float2bfloat16(w);
    g_Wout_hi[i] = hi;
    g_Wout_lo[i] = __float2bfloat16(w - __bfloat162float(hi));
}

// ------------------------------ GEMM ---------------------------------------
// C[M,N] = (A0 (+A1)) @ (B0 + B1)^T    all K-contiguous row-major.
// ALO=false: A0*(B0+B1).  ALO=true: A0*B0 + A0*B1 + A1*B0.
// Tiles: BM=BN=128, BK=32, 256 threads, warp grid 4(m) x 2(n),
// each warp 32x64 via m16n8k16 fragments loaded straight from padded smem.
#define GTEL (128 * 40)            // elems per smem tile (row stride 40 bf16)
#define GSTAGE (4 * GTEL)          // A0,A1,B0,B1 slots
#define GEMM_SMEM (2 * GSTAGE * 2) // bytes (2 stages, bf16)

template <bool ALO>
__global__ __launch_bounds__(256) void gemm_kernel(
    const __nv_bfloat16* __restrict__ A0, const __nv_bfloat16* __restrict__ A1,
    const __nv_bfloat16* __restrict__ B0, const __nv_bfloat16* __restrict__ B1,
    float* __restrict__ C, int M, int N, int K)
{
    extern __shared__ __nv_bfloat16 smb[];
    const int tid = threadIdx.x;
    const int lane = tid & 31, wid = tid >> 5;
    const int g = lane >> 2, q = lane & 3;
    const int wm = wid & 3, wn = wid >> 2;
    const int bm = blockIdx.y * 128, bn = blockIdx.x * 128;

    float acc[2][8][4];
#pragma unroll
    for (int a = 0; a < 2; a++)
#pragma unroll
        for (int b = 0; b < 8; b++)
#pragma unroll
            for (int c = 0; c < 4; c++) acc[a][b][c] = 0.f;

    const __nv_bfloat16* gA0 = A0 + (size_t)bm * K;
    const __nv_bfloat16* gA1 = ALO ? (A1 + (size_t)bm * K) : nullptr;
    const __nv_bfloat16* gB0 = B0 + (size_t)bn * K;
    const __nv_bfloat16* gB1 = B1 + (size_t)bn * K;

    auto load_stage = [&](int st, int k0) {
        __nv_bfloat16* base = smb + st * GSTAGE;
#pragma unroll
        for (int i = 0; i < 2; i++) {
            int ch = tid + i * 256;
            int r = ch >> 2, cc = ch & 3;
            size_t go = (size_t)r * K + k0 + cc * 8;
            int so = r * 40 + cc * 8;
            cp16(base + so, gA0 + go);
            if (ALO) cp16(base + GTEL + so, gA1 + go);
            cp16(base + 2 * GTEL + so, gB0 + go);
            cp16(base + 3 * GTEL + so, gB1 + go);
        }
        cp_commit();
    };

    load_stage(0, 0);
    const int KT = K >> 5;
    for (int kt = 0; kt < KT; kt++) {
        if (kt + 1 < KT) load_stage((kt + 1) & 1, (kt + 1) << 5);
        else cp_commit();
        asm volatile("cp.async.wait_group 1;\n");
        __syncthreads();
        const __nv_bfloat16* base = smb + (kt & 1) * GSTAGE;
#pragma unroll
        for (int ks = 0; ks < 2; ks++) {
            const int k0 = ks * 16;
            uint32_t a[2][4], al[2][4];
#pragma unroll
            for (int mi = 0; mi < 2; mi++) {
                const __nv_bfloat16* pa = base + (wm * 32 + mi * 16 + g) * 40 + k0 + 2 * q;
                a[mi][0] = lds32(pa);
                a[mi][1] = lds32(pa + 8 * 40);
                a[mi][2] = lds32(pa + 8);
                a[mi][3] = lds32(pa + 8 * 40 + 8);
                if (ALO) {
                    const __nv_bfloat16* pl = pa + GTEL;
                    al[mi][0] = lds32(pl);
                    al[mi][1] = lds32(pl + 8 * 40);
                    al[mi][2] = lds32(pl + 8);
                    al[mi][3] = lds32(pl + 8 * 40 + 8);
                }
            }
#pragma unroll
            for (int ni = 0; ni < 8; ni++) {
                const __nv_bfloat16* pb = base + 2 * GTEL + (wn * 64 + ni * 8 + g) * 40 + k0 + 2 * q;
                uint32_t b0 = lds32(pb), b1 = lds32(pb + 8);
                uint32_t c0 = lds32(pb + GTEL), c1 = lds32(pb + GTEL + 8);
#pragma unroll
                for (int mi = 0; mi < 2; mi++) {
                    mma16816(acc[mi][ni], a[mi], b0, b1);
                    mma16816(acc[mi][ni], a[mi], c0, c1);
                    if (ALO) mma16816(acc[mi][ni], al[mi], b0, b1);
                }
            }
        }
        __syncthreads();
    }
#pragma unroll
    for (int mi = 0; mi < 2; mi++) {
        int r0 = bm + wm * 32 + mi * 16 + g;
#pragma unroll
        for (int ni = 0; ni < 8; ni++) {
            int cc = bn + wn * 64 + ni * 8 + 2 * q;
            float* p = C + (size_t)r0 * N + cc;
            p[0] = acc[mi][ni][0];
            p[1] = acc[mi][ni][1];
            p += 8 * (size_t)N;
            p[0] = acc[mi][ni][2];
            p[1] = acc[mi][ni][3];
        }
    }
}

// ------------------------------ K2: conv -----------------------------------
__global__ void k_conv(const float* __restrict__ cw, const float* __restrict__ cb) {
    int c = blockIdx.x * 256 + threadIdx.x;     // < 2304
    int t0 = blockIdx.y * 64;
    float w0 = cw[c * 4 + 0], w1 = cw[c * 4 + 1], w2 = cw[c * 4 + 2], w3 = cw[c * 4 + 3];
    float b = cb[c];
    const float* col = g_zx + DI + c;           // x/B/C start at column 2048
    float v0 = (t0 >= 3) ? col[(size_t)(t0 - 3) * DIPP] : 0.f;
    float v1 = (t0 >= 2) ? col[(size_t)(t0 - 2) * DIPP] : 0.f;
    float v2 = (t0 >= 1) ? col[(size_t)(t0 - 1) * DIPP] : 0.f;
    for (int t = t0; t < t0 + 64; t++) {
        float v3 = col[(size_t)t * DIPP];
        float s = w0 * v0 + w1 * v1 + w2 * v2 + w3 * v3 + b;
        g_xc[(size_t)t * DCI + c] = silu(s);
        v0 = v1; v1 = v2; v2 = v3;
    }
}

// ------------------------------ K2b: dt + log-decay cumsum ------------------
__global__ void k_dt(const float* __restrict__ dt_bias, const float* __restrict__ A_log) {
    int c = blockIdx.x, h = blockIdx.y, t = threadIdx.x;     // 128 threads
    __shared__ float s[CH];
    float raw = g_zx[(size_t)(c * CH + t) * DIPP + 4352 + h] + dt_bias[h];
    float dtsp = (raw > 20.f) ? raw : log1pf(expf(raw));
    float la = dtsp * (-expf(A_log[h]));
    s[t] = la;
    __syncthreads();
    for (int off = 1; off < CH; off <<= 1) {
        float v = (t >= off) ? s[t - off] : 0.f;
        __syncthreads();
        s[t] += v;
        __syncthreads();
    }
    int base = (c * NH + h) * CH;
    g_dts[base + t] = dtsp;
    g_cumS[base + t] = s[t];
}

// ------------------------------ K3a: per-chunk local states -----------------
__global__ __launch_bounds__(256) void k_states() {
    int c = blockIdx.x, h = blockIdx.y, t0 = c * CH;
    __shared__ float xs[16 * 64], bs[16 * 128], ws[16];
    int tid = threadIdx.x;
    int pg = tid >> 4, ng = tid & 15;           // p0 = pg*4, n0 = ng*8
    float acc[4][8];
#pragma unroll
    for (int i = 0; i < 4; i++)
#pragma unroll
        for (int j = 0; j < 8; j++) acc[i][j] = 0.f;
    int sb = (c * NH + h) * CH;
    float Send = g_cumS[sb + CH - 1];
    for (int st = 0; st < 8; st++) {
#pragma unroll
        for (int r = 0; r < 4; r++) {
            int idx = r * 256 + tid;
            int s = idx >> 6, p = idx & 63;
            xs[idx] = g_xc[(size_t)(t0 + st * 16 + s) * DCI + h * HD + p];
        }
#pragma unroll
        for (int r = 0; r < 8; r++) {
            int idx = r * 256 + tid;
            int s = idx >> 7, n = idx & 127;
            bs[idx] = g_xc[(size_t)(t0 + st * 16 + s) * DCI + DI + n];
        }
        if (tid < 16) {
            int s = st * 16 + tid;
            ws[tid] = expf(Send - g_cumS[sb + s]) * g_dts[sb + s];
        }
        __syncthreads();
#pragma unroll
        for (int s = 0; s < 16; s++) {
            float w = ws[s];
            float xv[4], bv[8];
#pragma unroll
            for (int i = 0; i < 4; i++) xv[i] = w * xs[s * 64 + pg * 4 + i];
#pragma unroll
            for (int j = 0; j < 8; j++) bv[j] = bs[s * 128 + ng * 8 + j];
#pragma unroll
            for (int i = 0; i < 4; i++)
#pragma unroll
                for (int j = 0; j < 8; j++) acc[i][j] += xv[i] * bv[j];
        }
        __syncthreads();
    }
    size_t base = (size_t)(c * NH + h) * (HD * DS);
#pragma unroll
    for (int i = 0; i < 4; i++)
#pragma unroll
        for (int j = 0; j < 8; j++)
            g_Sloc[base + (pg * 4 + i) * DS + ng * 8 + j] = acc[i][j];
}

// ------------------------------ K3b: propagate chunk states -----------------
__global__ void k_prop() {
    int idx = blockIdx.x * 256 + threadIdx.x;   // < NH*HD*DS = 262144
    int h = idx >> 13;
    float hcur = 0.f;
    for (int c = 0; c < NC; c++) {
        size_t off = (size_t)c * (NH * HD * DS) + idx;
        g_hinit[off] = hcur;
        float tot = expf(g_cumS[(c * NH + h) * CH + CH - 1]);
        hcur = tot * hcur + g_Sloc[off];
    }
}

// ------------------------------ K3c: per-chunk outputs ----------------------
#define KOUT_SMEM ((128 * 132 + 256 + 2 * 2176) * 4)
__global__ __launch_bounds__(256) void k_out(const float* __restrict__ Dp) {
    int c = blockIdx.x, h = blockIdx.y, t0 = c * CH;
    extern __shared__ float sm[];
    float* Gs = sm;                      // 128 x 132
    float* Sa = Gs + 128 * 132;          // 128
    float* Da = Sa + 128;                // 128
    float* stA = Da + 128;               // 128 x 17
    float* stB = stA + 2176;             // 128 x 17
    int tid = threadIdx.x;
    int sb = (c * NH + h) * CH;
    if (tid < 128) {
        Sa[tid] = g_cumS[sb + tid];
        Da[tid] = g_dts[sb + tid];
    }
    __syncthreads();

    // pass 1: G[t][s] = C_t . B_s
    {
        int tg = tid >> 4, sg = tid & 15;
        float acc[8][8];
#pragma unroll
        for (int i = 0; i < 8; i++)
#pragma unroll
            for (int j = 0; j < 8; j++) acc[i][j] = 0.f;
        for (int nt = 0; nt < 8; nt++) {
#pragma unroll
            for (int r = 0; r < 8; r++) {
                int idx = r * 256 + tid;
                int t = idx >> 4, nn = idx & 15;
                stA[t * 17 + nn] = g_xc[(size_t)(t0 + t) * DCI + DI + DS + nt * 16 + nn]; // C
                stB[t * 17 + nn] = g_xc[(size_t)(t0 + t) * DCI + DI + nt * 16 + nn];      // B
            }
            __syncthreads();
#pragma unroll
            for (int nn = 0; nn < 16; nn++) {
                float cv[8], bv[8];
#pragma unroll
                for (int i = 0; i < 8; i++) cv[i] = stA[(tg * 8 + i) * 17 + nn];
#pragma unroll
                for (int j = 0; j < 8; j++) bv[j] = stB[(sg * 8 + j) * 17 + nn];
#pragma unroll
                for (int i = 0; i < 8; i++)
#pragma unroll
                    for (int j = 0; j < 8; j++) acc[i][j] += cv[i] * bv[j];
            }
            __syncthreads();
        }
#pragma unroll
        for (int i = 0; i < 8; i++)
#pragma unroll
            for (int j = 0; j < 8; j++) {
                int t = tg * 8 + i, s = sg * 8 + j;
                float gmv = (s <= t) ? acc[i][j] * expf(Sa[t] - Sa[s]) * Da[s] : 0.f;
                Gs[t * 132 + s] = gmv;
            }
    }
    __syncthreads();

    // pass 2: Y = G @ X  + exp(S_t) * C @ h_init^T + D*x
    int tg2 = tid >> 3, pg = tid & 7;   // t = tg2*4+i, p = pg*8+j
    float acc2[4][8];
#pragma unroll
    for (int i = 0; i < 4; i++)
#pragma unroll
        for (int j = 0; j < 8; j++) acc2[i][j] = 0.f;

    for (int st = 0; st < 8; st++) {
#pragma unroll
        for (int r = 0; r < 4; r++) {
            int idx = r * 256 + tid;
            int s = idx >> 6, p = idx & 63;
            stA[idx] = g_xc[(size_t)(t0 + st * 16 + s) * DCI + h * HD + p];
        }
        __syncthreads();
#pragma unroll
        for (int ss = 0; ss < 16; ss++) {
            int s = st * 16 + ss;
            float gv[4], xv[8];
#pragma unroll
            for (int i = 0; i < 4; i++) gv[i] = Gs[(tg2 * 4 + i) * 132 + s];
#pragma unroll
            for (int j = 0; j < 8; j++) xv[j] = stA[ss * 64 + pg * 8 + j];
#pragma unroll
            for (int i = 0; i < 4; i++)
#pragma unroll
                for (int j = 0; j < 8; j++) acc2[i][j] += gv[i] * xv[j];
        }
        __syncthreads();
    }

    for (int nt = 0; nt < 8; nt++) {
#pragma unroll
        for (int r = 0; r < 8; r++) {
            int idx = r * 256 + tid;
            int t = idx >> 4, nn = idx & 15;
            stA[t * 17 + nn] = expf(Sa[t]) *
                g_xc[(size_t)(t0 + t) * DCI + DI + DS + nt * 16 + nn];   // scaled C
        }
#pragma unroll
        for (int r = 0; r < 4; r++) {
            int idx = r * 256 + tid;
            int p = idx >> 4, nn = idx & 15;
            stB[p * 17 + nn] =
                g_hinit[(size_t)c * (NH * HD * DS) + h * (HD * DS) + p * DS + nt * 16 + nn];
        }
        __syncthreads();
#pragma unroll
        for (int nn = 0; nn < 16; nn++) {
            float cv[4], hv[8];
#pragma unroll
            for (int i = 0; i < 4; i++) cv[i] = stA[(tg2 * 4 + i) * 17 + nn];
#pragma unroll
            for (int j = 0; j < 8; j++) hv[j] = stB[(pg * 8 + j) * 17 + nn];
#pragma unroll
            for (int i = 0; i < 4; i++)
#pragma unroll
                for (int j = 0; j < 8; j++) acc2[i][j] += cv[i] * hv[j];
        }
        __syncthreads();
    }

    float Dh = Dp[h];
#pragma unroll
    for (int i = 0; i < 4; i++)
#pragma unroll
        for (int j = 0; j < 8; j++) {
            int t = tg2 * 4 + i, p = pg * 8 + j;
            float x = g_xc[(size_t)(t0 + t) * DCI + h * HD + p];
            g_y[(size_t)(t0 + t) * DI + h * HD + p] = acc2[i][j] + Dh * x;
        }
}

// ------------------------------ K4: rmsnorm + gate --------------------------
__global__ void k_norm(const float* __restrict__ nw, const float* __restrict__ nb) {
    int t = blockIdx.x, tid = threadIdx.x;     // 256 threads
    __shared__ float red[256];
    float ss = 0.f;
    for (int i = tid; i < DI; i += 256) {
        float v = g_y[(size_t)t * DI + i];
        ss += v * v;
    }
    red[tid] = ss;
    __syncthreads();
    for (int o = 128; o > 0; o >>= 1) {
        if (tid < o) red[tid] += red[tid + o];
        __syncthreads();
    }
    float inv = rsqrtf(red[0] / (float)DI + 1e-6f);
    for (int i = tid; i < DI; i += 256) {
        float v = g_y[(size_t)t * DI + i] * inv * nw[i] + nb[i];
        float z = g_zx[(size_t)t * DIPP + i];
        float o = v * silu(z);
        __nv_bfloat16 hi = __float2bfloat16(o);
        g_yg_hi[(size_t)t * DI + i] = hi;
        g_yg_lo[(size_t)t * DI + i] = __float2bfloat16(o - __bfloat162float(hi));
    }
}

// ------------------------------ host ----------------------------------------
extern "C" void kernel_launch(void* const* d_in, const int* in_sizes, int n_in,
                              void* d_out, int out_size) {
    const float* u       = (const float*)d_in[0];
    const float* W_in    = (const float*)d_in[1];
    const float* conv_w  = (const float*)d_in[2];
    const float* conv_b  = (const float*)d_in[3];
    const float* W_out   = (const float*)d_in[4];
    const float* norm_w  = (const float*)d_in[5];
    const float* norm_b  = (const float*)d_in[6];
    const float* dt_bias = (const float*)d_in[7];
    const float* A_log   = (const float*)d_in[8];
    const float* Dp      = (const float*)d_in[9];
    float* out = (float*)d_out;

    void *p_ub, *p_wih, *p_wil, *p_woh, *p_wol, *p_zx, *p_ygh, *p_ygl;
    cudaGetSymbolAddress(&p_ub, g_ub);
    cudaGetSymbolAddress(&p_wih, g_Win_hi);
    cudaGetSymbolAddress(&p_wil, g_Win_lo);
    cudaGetSymbolAddress(&p_woh, g_Wout_hi);
    cudaGetSymbolAddress(&p_wol, g_Wout_lo);
    cudaGetSymbolAddress(&p_zx, g_zx);
    cudaGetSymbolAddress(&p_ygh, g_yg_hi);
    cudaGetSymbolAddress(&p_ygl, g_yg_lo);

    cudaFuncSetAttribute(gemm_kernel<false>,
                         cudaFuncAttributeMaxDynamicSharedMemorySize, GEMM_SMEM);
    cudaFuncSetAttribute(gemm_kernel<true>,
                         cudaFuncAttributeMaxDynamicSharedMemorySize, GEMM_SMEM);
    cudaFuncSetAttribute(k_out,
                         cudaFuncAttributeMaxDynamicSharedMemorySize, KOUT_SMEM);

    k_cvt_u<<<4096, 256>>>(u);
    k_split_win<<<(DIPP * DM + 255) / 256, 256>>>(W_in);
    k_split_wout<<<(DM * DI + 255) / 256, 256>>>(W_out);

    gemm_kernel<false><<<dim3(DIPP / 128, SEQ / 128), 256, GEMM_SMEM>>>(
        (const __nv_bfloat16*)p_ub, nullptr,
        (const __nv_bfloat16*)p_wih, (const __nv_bfloat16*)p_wil,
        (float*)p_zx, SEQ, DIPP, DM);

    k_conv<<<dim3(DCI / 256, SEQ / 64), 256>>>(conv_w, conv_b);
    k_dt<<<dim3(NC, NH), CH>>>(dt_bias, A_log);
    k_states<<<dim3(NC, NH), 256>>>();
    k_prop<<<(NH * HD * DS) / 256, 256>>>();
    k_out<<<dim3(NC, NH), 256, KOUT_SMEM>>>(Dp);
    k_norm<<<SEQ, 256>>>(norm_w, norm_b);

    gemm_kernel<true><<<dim3(DM / 128, SEQ / 128), 256, GEMM_SMEM>>>(
        (const __nv_bfloat16*)p_ygh, (const __nv_bfloat16*)p_ygl,
        (const __nv_bfloat16*)p_woh, (const __nv_bfloat16*)p_wol,
        out, SEQ, DM, DI);
}

// round 3
// speedup vs baseline: 1.2958x; 1.2958x over previous
#include <cuda_runtime.h>
#include <cuda_bf16.h>
#include <cstdint>
#include <cstddef>

// ---------------------------------------------------------------------------
// Mamba2 block forward, SEQ=4096, D_MODEL=1024.
//  K0  : convert u->bf16; split W_in / W_out into bf16 hi+lo
//  K1  : GEMM1  zxbcdt = ub @ W_in^T          (split-B bf16 tensor cores)
//  K2  : causal depthwise conv(4) + SiLU
//  K2b : dt softplus, per-chunk log-decay cumsum
//  K3a : k_states — per-chunk local states via split-bf16 mma (S = Xw^T @ B)
//  K3b : sequential chunk-state propagation
//  K3c : k_out — G=C.B^T (mma), mask/decay, Y=G@X + Ce@h0^T (mma), +D*x
//  K4  : RMSNorm + silu(z) gate -> yg hi/lo bf16
//  K5  : GEMM2  out = yg @ W_out^T            (split-A and split-B)
// ---------------------------------------------------------------------------

#define SEQ   4096
#define DM    1024
#define DIP   4384
#define DIPP  4480
#define DI    2048
#define DCI   2304
#define NH    32
#define HD    64
#define DS    128
#define CH    128
#define NC    32

// ------------------------------ scratch ------------------------------------
__device__ __nv_bfloat16 g_ub[SEQ * DM];
__device__ __nv_bfloat16 g_Win_hi[DIPP * DM];
__device__ __nv_bfloat16 g_Win_lo[DIPP * DM];
__device__ __nv_bfloat16 g_Wout_hi[DM * DI];
__device__ __nv_bfloat16 g_Wout_lo[DM * DI];
__device__ float g_zx[(size_t)SEQ * DIPP];
__device__ float g_xc[(size_t)SEQ * DCI];
__device__ float g_dts[NC * NH * CH];
__device__ float g_cumS[NC * NH * CH];
__device__ float g_Sloc[(size_t)NC * NH * HD * DS];
__device__ float g_hinit[(size_t)NC * NH * HD * DS];
__device__ float g_y[(size_t)SEQ * DI];
__device__ __nv_bfloat16 g_yg_hi[(size_t)SEQ * DI];
__device__ __nv_bfloat16 g_yg_lo[(size_t)SEQ * DI];

// ------------------------------ helpers ------------------------------------
__device__ __forceinline__ void cp16(void* smem, const void* gmem) {
    uint32_t s = (uint32_t)__cvta_generic_to_shared(smem);
    asm volatile("cp.async.cg.shared.global [%0], [%1], 16;\n" :: "r"(s), "l"(gmem));
}
__device__ __forceinline__ void cp_commit() { asm volatile("cp.async.commit_group;\n"); }

__device__ __forceinline__ uint32_t lds32(const __nv_bfloat16* p) {
    return *reinterpret_cast<const uint32_t*>(p);
}

__device__ __forceinline__ void mma16816(float* d, const uint32_t* a, uint32_t b0, uint32_t b1) {
    asm volatile(
        "mma.sync.aligned.m16n8k16.row.col.f32.bf16.bf16.f32 "
        "{%0,%1,%2,%3}, {%4,%5,%6,%7}, {%8,%9}, {%0,%1,%2,%3};\n"
        : "+f"(d[0]), "+f"(d[1]), "+f"(d[2]), "+f"(d[3])
        : "r"(a[0]), "r"(a[1]), "r"(a[2]), "r"(a[3]), "r"(b0), "r"(b1));
}

__device__ __forceinline__ float silu(float x) { return x / (1.f + expf(-x)); }

__device__ __forceinline__ void split_store(__nv_bfloat16* hi, __nv_bfloat16* lo, float v) {
    __nv_bfloat16 h = __float2bfloat16(v);
    *hi = h;
    *lo = __float2bfloat16(v - __bfloat162float(h));
}

// ------------------------------ K0 -----------------------------------------
__global__ void k_cvt_u(const float* __restrict__ u) {
    for (int i = blockIdx.x * blockDim.x + threadIdx.x; i < SEQ * DM;
         i += gridDim.x * blockDim.x)
        g_ub[i] = __float2bfloat16(u[i]);
}

__global__ void k_split_win(const float* __restrict__ W) {
    int i = blockIdx.x * blockDim.x + threadIdx.x;
    if (i >= DIPP * DM) return;
    int r = i >> 10;
    int c = i & 1023;
    float w = (r < DIP) ? W[r * DM + c] : 0.f;
    split_store(&g_Win_hi[i], &g_Win_lo[i], w);
}

__global__ void k_split_wout(const float* __restrict__ W) {
    int i = blockIdx.x * blockDim.x + threadIdx.x;
    if (i >= DM * DI) return;
    split_store(&g_Wout_hi[i], &g_Wout_lo[i], W[i]);
}

// ------------------------------ GEMM (unchanged, validated) -----------------
#define GTEL (128 * 40)
#define GSTAGE (4 * GTEL)
#define GEMM_SMEM (2 * GSTAGE * 2)

template <bool ALO>
__global__ __launch_bounds__(256) void gemm_kernel(
    const __nv_bfloat16* __restrict__ A0, const __nv_bfloat16* __restrict__ A1,
    const __nv_bfloat16* __restrict__ B0, const __nv_bfloat16* __restrict__ B1,
    float* __restrict__ C, int M, int N, int K)
{
    extern __shared__ __nv_bfloat16 smb[];
    const int tid = threadIdx.x;
    const int lane = tid & 31, wid = tid >> 5;
    const int g = lane >> 2, q = lane & 3;
    const int wm = wid & 3, wn = wid >> 2;
    const int bm = blockIdx.y * 128, bn = blockIdx.x * 128;

    float acc[2][8][4];
#pragma unroll
    for (int a = 0; a < 2; a++)
#pragma unroll
        for (int b = 0; b < 8; b++)
#pragma unroll
            for (int c2 = 0; c2 < 4; c2++) acc[a][b][c2] = 0.f;

    const __nv_bfloat16* gA0 = A0 + (size_t)bm * K;
    const __nv_bfloat16* gA1 = ALO ? (A1 + (size_t)bm * K) : nullptr;
    const __nv_bfloat16* gB0 = B0 + (size_t)bn * K;
    const __nv_bfloat16* gB1 = B1 + (size_t)bn * K;

    auto load_stage = [&](int st, int k0) {
        __nv_bfloat16* base = smb + st * GSTAGE;
#pragma unroll
        for (int i = 0; i < 2; i++) {
            int ch = tid + i * 256;
            int r = ch >> 2, cc = ch & 3;
            size_t go = (size_t)r * K + k0 + cc * 8;
            int so = r * 40 + cc * 8;
            cp16(base + so, gA0 + go);
            if (ALO) cp16(base + GTEL + so, gA1 + go);
            cp16(base + 2 * GTEL + so, gB0 + go);
            cp16(base + 3 * GTEL + so, gB1 + go);
        }
        cp_commit();
    };

    load_stage(0, 0);
    const int KT = K >> 5;
    for (int kt = 0; kt < KT; kt++) {
        if (kt + 1 < KT) load_stage((kt + 1) & 1, (kt + 1) << 5);
        else cp_commit();
        asm volatile("cp.async.wait_group 1;\n");
        __syncthreads();
        const __nv_bfloat16* base = smb + (kt & 1) * GSTAGE;
#pragma unroll
        for (int ks = 0; ks < 2; ks++) {
            const int k0 = ks * 16;
            uint32_t a[2][4], al[2][4];
#pragma unroll
            for (int mi = 0; mi < 2; mi++) {
                const __nv_bfloat16* pa = base + (wm * 32 + mi * 16 + g) * 40 + k0 + 2 * q;
                a[mi][0] = lds32(pa);
                a[mi][1] = lds32(pa + 8 * 40);
                a[mi][2] = lds32(pa + 8);
                a[mi][3] = lds32(pa + 8 * 40 + 8);
                if (ALO) {
                    const __nv_bfloat16* pl = pa + GTEL;
                    al[mi][0] = lds32(pl);
                    al[mi][1] = lds32(pl + 8 * 40);
                    al[mi][2] = lds32(pl + 8);
                    al[mi][3] = lds32(pl + 8 * 40 + 8);
                }
            }
#pragma unroll
            for (int ni = 0; ni < 8; ni++) {
                const __nv_bfloat16* pb = base + 2 * GTEL + (wn * 64 + ni * 8 + g) * 40 + k0 + 2 * q;
                uint32_t b0 = lds32(pb), b1 = lds32(pb + 8);
                uint32_t c0 = lds32(pb + GTEL), c1 = lds32(pb + GTEL + 8);
#pragma unroll
                for (int mi = 0; mi < 2; mi++) {
                    mma16816(acc[mi][ni], a[mi], b0, b1);
                    mma16816(acc[mi][ni], a[mi], c0, c1);
                    if (ALO) mma16816(acc[mi][ni], al[mi], b0, b1);
                }
            }
        }
        __syncthreads();
    }
#pragma unroll
    for (int mi = 0; mi < 2; mi++) {
        int r0 = bm + wm * 32 + mi * 16 + g;
#pragma unroll
        for (int ni = 0; ni < 8; ni++) {
            int cc = bn + wn * 64 + ni * 8 + 2 * q;
            float* p = C + (size_t)r0 * N + cc;
            p[0] = acc[mi][ni][0];
            p[1] = acc[mi][ni][1];
            p += 8 * (size_t)N;
            p[0] = acc[mi][ni][2];
            p[1] = acc[mi][ni][3];
        }
    }
}

// ------------------------------ K2: conv -----------------------------------
__global__ void k_conv(const float* __restrict__ cw, const float* __restrict__ cb) {
    int c = blockIdx.x * 256 + threadIdx.x;
    int t0 = blockIdx.y * 64;
    float w0 = cw[c * 4 + 0], w1 = cw[c * 4 + 1], w2 = cw[c * 4 + 2], w3 = cw[c * 4 + 3];
    float b = cb[c];
    const float* col = g_zx + DI + c;
    float v0 = (t0 >= 3) ? col[(size_t)(t0 - 3) * DIPP] : 0.f;
    float v1 = (t0 >= 2) ? col[(size_t)(t0 - 2) * DIPP] : 0.f;
    float v2 = (t0 >= 1) ? col[(size_t)(t0 - 1) * DIPP] : 0.f;
    for (int t = t0; t < t0 + 64; t++) {
        float v3 = col[(size_t)t * DIPP];
        float s = w0 * v0 + w1 * v1 + w2 * v2 + w3 * v3 + b;
        g_xc[(size_t)t * DCI + c] = silu(s);
        v0 = v1; v1 = v2; v2 = v3;
    }
}

// ------------------------------ K2b: dt + log-decay cumsum ------------------
__global__ void k_dt(const float* __restrict__ dt_bias, const float* __restrict__ A_log) {
    int c = blockIdx.x, h = blockIdx.y, t = threadIdx.x;
    __shared__ float s[CH];
    float raw = g_zx[(size_t)(c * CH + t) * DIPP + 4352 + h] + dt_bias[h];
    float dtsp = (raw > 20.f) ? raw : log1pf(expf(raw));
    float la = dtsp * (-expf(A_log[h]));
    s[t] = la;
    __syncthreads();
    for (int off = 1; off < CH; off <<= 1) {
        float v = (t >= off) ? s[t - off] : 0.f;
        __syncthreads();
        s[t] += v;
        __syncthreads();
    }
    int base = (c * NH + h) * CH;
    g_dts[base + t] = dtsp;
    g_cumS[base + t] = s[t];
}

// ------------------------------ K3a: local states via mma -------------------
// S[p,n] = sum_s (w_s x[s,p]) * B[s,n]; M=64(p), N=128(n), K=128(s), 3-pass.
__global__ __launch_bounds__(256) void k_states() {
    __shared__ __nv_bfloat16 XTh[64 * 36], XTl[64 * 36];
    __shared__ __nv_bfloat16 BTh[128 * 36], BTl[128 * 36];
    __shared__ float wv[128];
    int c = blockIdx.x, h = blockIdx.y, t0 = c * CH;
    int tid = threadIdx.x, lane = tid & 31, w = tid >> 5;
    int g = lane >> 2, q = lane & 3;
    int wr = w & 1, wc = w >> 1;
    int sb = (c * NH + h) * CH;
    if (tid < 128) {
        float Send = g_cumS[sb + CH - 1];
        wv[tid] = expf(Send - g_cumS[sb + tid]) * g_dts[sb + tid];
    }
    float acc[2][4][4] = {};
    for (int kt = 0; kt < 4; kt++) {
        __syncthreads();
#pragma unroll
        for (int i = 0; i < 8; i++) {           // X^T staging (w-scaled)
            int idx = tid + i * 256;
            int s = idx >> 6, p = idx & 63;
            float v = wv[kt * 32 + s] *
                      g_xc[(size_t)(t0 + kt * 32 + s) * DCI + h * HD + p];
            split_store(&XTh[p * 36 + s], &XTl[p * 36 + s], v);
        }
#pragma unroll
        for (int i = 0; i < 16; i++) {          // B^T staging
            int idx = tid + i * 256;
            int s = idx >> 7, n = idx & 127;
            float v = g_xc[(size_t)(t0 + kt * 32 + s) * DCI + DI + n];
            split_store(&BTh[n * 36 + s], &BTl[n * 36 + s], v);
        }
        __syncthreads();
#pragma unroll
        for (int ks = 0; ks < 2; ks++) {
            int k0 = ks * 16 + 2 * q;
            uint32_t ah[2][4], al[2][4];
#pragma unroll
            for (int mi = 0; mi < 2; mi++) {
                const __nv_bfloat16* pa = XTh + (wr * 32 + mi * 16 + g) * 36 + k0;
                ah[mi][0] = lds32(pa);        ah[mi][1] = lds32(pa + 8 * 36);
                ah[mi][2] = lds32(pa + 8);    ah[mi][3] = lds32(pa + 8 * 36 + 8);
                const __nv_bfloat16* pl = XTl + (wr * 32 + mi * 16 + g) * 36 + k0;
                al[mi][0] = lds32(pl);        al[mi][1] = lds32(pl + 8 * 36);
                al[mi][2] = lds32(pl + 8);    al[mi][3] = lds32(pl + 8 * 36 + 8);
            }
#pragma unroll
            for (int ni = 0; ni < 4; ni++) {
                const __nv_bfloat16* pb = BTh + (wc * 32 + ni * 8 + g) * 36 + k0;
                uint32_t bh0 = lds32(pb), bh1 = lds32(pb + 8);
                const __nv_bfloat16* pbl = BTl + (wc * 32 + ni * 8 + g) * 36 + k0;
                uint32_t bl0 = lds32(pbl), bl1 = lds32(pbl + 8);
#pragma unroll
                for (int mi = 0; mi < 2; mi++) {
                    mma16816(acc[mi][ni], ah[mi], bh0, bh1);
                    mma16816(acc[mi][ni], ah[mi], bl0, bl1);
                    mma16816(acc[mi][ni], al[mi], bh0, bh1);
                }
            }
        }
    }
    size_t base = (size_t)(c * NH + h) * (HD * DS);
#pragma unroll
    for (int mi = 0; mi < 2; mi++) {
        int p0 = wr * 32 + mi * 16 + g;
#pragma unroll
        for (int ni = 0; ni < 4; ni++) {
            int n0 = wc * 32 + ni * 8 + 2 * q;
            g_Sloc[base + p0 * DS + n0]           = acc[mi][ni][0];
            g_Sloc[base + p0 * DS + n0 + 1]       = acc[mi][ni][1];
            g_Sloc[base + (p0 + 8) * DS + n0]     = acc[mi][ni][2];
            g_Sloc[base + (p0 + 8) * DS + n0 + 1] = acc[mi][ni][3];
        }
    }
}

// ------------------------------ K3b: propagate chunk states -----------------
__global__ void k_prop() {
    int idx = blockIdx.x * 256 + threadIdx.x;
    int h = idx >> 13;
    float hcur = 0.f;
    for (int c = 0; c < NC; c++) {
        size_t off = (size_t)c * (NH * HD * DS) + idx;
        g_hinit[off] = hcur;
        float tot = expf(g_cumS[(c * NH + h) * CH + CH - 1]);
        hcur = tot * hcur + g_Sloc[off];
    }
}

// ------------------------------ K3c: per-chunk outputs via mma --------------
// smem (bf16 elems): Gh[128*136] Gl[128*136] Ah[128*36] Al Bh Bl | Sa Da f32
#define KO_ELEMS (2 * 17408 + 4 * 4608)
#define KOUT_SMEM (KO_ELEMS * 2 + 1024)
__global__ __launch_bounds__(256) void k_out(const float* __restrict__ Dp) {
    extern __shared__ __nv_bfloat16 smb[];
    __nv_bfloat16* Gh = smb;
    __nv_bfloat16* Gl = smb + 17408;
    __nv_bfloat16* Ah = smb + 34816;
    __nv_bfloat16* Al = smb + 39424;
    __nv_bfloat16* Bh = smb + 44032;
    __nv_bfloat16* Bl = smb + 48640;
    float* Sa = (float*)(smb + KO_ELEMS);
    float* Da = Sa + 128;

    int c = blockIdx.x, h = blockIdx.y, t0 = c * CH;
    int tid = threadIdx.x, lane = tid & 31, w = tid >> 5;
    int g = lane >> 2, q = lane & 3;
    int sb = (c * NH + h) * CH;
    if (tid < 128) {
        Sa[tid] = g_cumS[sb + tid];
        Da[tid] = g_dts[sb + tid];
    }

    // ---- pass 1: G[t,s] = sum_n C[t,n] B[s,n] ----
    {
        int wr = w & 3, wc = w >> 2;           // t: 4x32, s: 2x64
        float acc[2][8][4] = {};
        for (int kt = 0; kt < 4; kt++) {
            __syncthreads();
#pragma unroll
            for (int i = 0; i < 16; i++) {
                int idx = tid + i * 256;
                int t = idx >> 5, n = idx & 31;
                size_t row = (size_t)(t0 + t) * DCI + DI + kt * 32 + n;
                split_store(&Ah[t * 36 + n], &Al[t * 36 + n], g_xc[row + DS]);  // C
                split_store(&Bh[t * 36 + n], &Bl[t * 36 + n], g_xc[row]);       // B
            }
            __syncthreads();
#pragma unroll
            for (int ks = 0; ks < 2; ks++) {
                int k0 = ks * 16 + 2 * q;
                uint32_t ah[2][4], al[2][4];
#pragma unroll
                for (int mi = 0; mi < 2; mi++) {
                    const __nv_bfloat16* pa = Ah + (wr * 32 + mi * 16 + g) * 36 + k0;
                    ah[mi][0] = lds32(pa);     ah[mi][1] = lds32(pa + 8 * 36);
                    ah[mi][2] = lds32(pa + 8); ah[mi][3] = lds32(pa + 8 * 36 + 8);
                    const __nv_bfloat16* pl = Al + (wr * 32 + mi * 16 + g) * 36 + k0;
                    al[mi][0] = lds32(pl);     al[mi][1] = lds32(pl + 8 * 36);
                    al[mi][2] = lds32(pl + 8); al[mi][3] = lds32(pl + 8 * 36 + 8);
                }
#pragma unroll
                for (int ni = 0; ni < 8; ni++) {
                    const __nv_bfloat16* pb = Bh + (wc * 64 + ni * 8 + g) * 36 + k0;
                    uint32_t bh0 = lds32(pb), bh1 = lds32(pb + 8);
                    const __nv_bfloat16* pbl = Bl + (wc * 64 + ni * 8 + g) * 36 + k0;
                    uint32_t bl0 = lds32(pbl), bl1 = lds32(pbl + 8);
#pragma unroll
                    for (int mi = 0; mi < 2; mi++) {
                        mma16816(acc[mi][ni], ah[mi], bh0, bh1);
                        mma16816(acc[mi][ni], ah[mi], bl0, bl1);
                        mma16816(acc[mi][ni], al[mi], bh0, bh1);
                    }
                }
            }
        }
        // mask + decay + split-store G
#pragma unroll
        for (int mi = 0; mi < 2; mi++) {
            int tA = wr * 32 + mi * 16 + g;
            float SaA = Sa[tA], SaB = Sa[tA + 8];
#pragma unroll
            for (int ni = 0; ni < 8; ni++) {
                int s0 = wc * 64 + ni * 8 + 2 * q;
#pragma unroll
                for (int jj = 0; jj < 2; jj++) {
                    int s = s0 + jj;
                    float ds = Da[s], Ss = Sa[s];
                    float v0 = (s <= tA)     ? acc[mi][ni][jj]     * expf(SaA - Ss) * ds : 0.f;
                    float v1 = (s <= tA + 8) ? acc[mi][ni][2 + jj] * expf(SaB - Ss) * ds : 0.f;
                    split_store(&Gh[tA * 136 + s],       &Gl[tA * 136 + s],       v0);
                    split_store(&Gh[(tA + 8) * 136 + s], &Gl[(tA + 8) * 136 + s], v1);
                }
            }
        }
    }
    __syncthreads();

    // ---- pass 2: Y[t,p] = sum_s G[t,s] X[s,p] + sum_n Ce[t,n] h0[p,n] ----
    int wr2 = w & 3, wc2 = w >> 2;             // t: 4x32, p: 2x32
    float acc2[2][4][4] = {};
    // term 1: A = G (k=s), B = X^T
    for (int kt = 0; kt < 4; kt++) {
        if (kt) __syncthreads();
#pragma unroll
        for (int i = 0; i < 8; i++) {
            int idx = tid + i * 256;
            int s = idx >> 6, p = idx & 63;
            float v = g_xc[(size_t)(t0 + kt * 32 + s) * DCI + h * HD + p];
            split_store(&Bh[p * 36 + s], &Bl[p * 36 + s], v);
        }
        __syncthreads();
#pragma unroll
        for (int ks = 0; ks < 2; ks++) {
            int kg = kt * 32 + ks * 16 + 2 * q;  // G column offset
            int kb = ks * 16 + 2 * q;
            uint32_t ah[2][4], al[2][4];
#pragma unroll
            for (int mi = 0; mi < 2; mi++) {
                const __nv_bfloat16* pa = Gh + (wr2 * 32 + mi * 16 + g) * 136 + kg;
                ah[mi][0] = lds32(pa);     ah[mi][1] = lds32(pa + 8 * 136);
                ah[mi][2] = lds32(pa + 8); ah[mi][3] = lds32(pa + 8 * 136 + 8);
                const __nv_bfloat16* pl = Gl + (wr2 * 32 + mi * 16 + g) * 136 + kg;
                al[mi][0] = lds32(pl);     al[mi][1] = lds32(pl + 8 * 136);
                al[mi][2] = lds32(pl + 8); al[mi][3] = lds32(pl + 8 * 136 + 8);
            }
#pragma unroll
            for (int ni = 0; ni < 4; ni++) {
                const __nv_bfloat16* pb = Bh + (wc2 * 32 + ni * 8 + g) * 36 + kb;
                uint32_t bh0 = lds32(pb), bh1 = lds32(pb + 8);
                const __nv_bfloat16* pbl = Bl + (wc2 * 32 + ni * 8 + g) * 36 + kb;
                uint32_t bl0 = lds32(pbl), bl1 = lds32(pbl + 8);
#pragma unroll
                for (int mi = 0; mi < 2; mi++) {
                    mma16816(acc2[mi][ni], ah[mi], bh0, bh1);
                    mma16816(acc2[mi][ni], ah[mi], bl0, bl1);
                    mma16816(acc2[mi][ni], al[mi], bh0, bh1);
                }
            }
        }
    }
    // term 2: A = exp(Sa[t])*C (k=n), B = h0[p,n]
    for (int kt = 0; kt < 4; kt++) {
        __syncthreads();
#pragma unroll
        for (int i = 0; i < 16; i++) {
            int idx = tid + i * 256;
            int t = idx >> 5, n = idx & 31;
            float v = expf(Sa[t]) *
                      g_xc[(size_t)(t0 + t) * DCI + DI + DS + kt * 32 + n];
            split_store(&Ah[t * 36 + n], &Al[t * 36 + n], v);
        }
#pragma unroll
        for (int i = 0; i < 8; i++) {
            int idx = tid + i * 256;
            int p = idx >> 5, n = idx & 31;
            float v = g_hinit[(size_t)c * (NH * HD * DS) + h * (HD * DS) + p * DS + kt * 32 + n];
            split_store(&Bh[p * 36 + n], &Bl[p * 36 + n], v);
        }
        __syncthreads();
#pragma unroll
        for (int ks = 0; ks < 2; ks++) {
            int k0 = ks * 16 + 2 * q;
            uint32_t ah[2][4], al[2][4];
#pragma unroll
            for (int mi = 0; mi < 2; mi++) {
                const __nv_bfloat16* pa = Ah + (wr2 * 32 + mi * 16 + g) * 36 + k0;
                ah[mi][0] = lds32(pa);     ah[mi][1] = lds32(pa + 8 * 36);
                ah[mi][2] = lds32(pa + 8); ah[mi][3] = lds32(pa + 8 * 36 + 8);
                const __nv_bfloat16* pl = Al + (wr2 * 32 + mi * 16 + g) * 36 + k0;
                al[mi][0] = lds32(pl);     al[mi][1] = lds32(pl + 8 * 36);
                al[mi][2] = lds32(pl + 8); al[mi][3] = lds32(pl + 8 * 36 + 8);
            }
#pragma unroll
            for (int ni = 0; ni < 4; ni++) {
                const __nv_bfloat16* pb = Bh + (wc2 * 32 + ni * 8 + g) * 36 + k0;
                uint32_t bh0 = lds32(pb), bh1 = lds32(pb + 8);
                const __nv_bfloat16* pbl = Bl + (wc2 * 32 + ni * 8 + g) * 36 + k0;
                uint32_t bl0 = lds32(pbl), bl1 = lds32(pbl + 8);
#pragma unroll
                for (int mi = 0; mi < 2; mi++) {
                    mma16816(acc2[mi][ni], ah[mi], bh0, bh1);
                    mma16816(acc2[mi][ni], ah[mi], bl0, bl1);
                    mma16816(acc2[mi][ni], al[mi], bh0, bh1);
                }
            }
        }
    }
    // epilogue: + D*x, write y
    float Dh = Dp[h];
#pragma unroll
    for (int mi = 0; mi < 2; mi++) {
        int t = wr2 * 32 + mi * 16 + g;
#pragma unroll
        for (int ni = 0; ni < 4; ni++) {
            int p0 = wc2 * 32 + ni * 8 + 2 * q;
#pragma unroll
            for (int jj = 0; jj < 2; jj++) {
                int p = p0 + jj;
                float x0 = g_xc[(size_t)(t0 + t) * DCI + h * HD + p];
                float x1 = g_xc[(size_t)(t0 + t + 8) * DCI + h * HD + p];
                g_y[(size_t)(t0 + t) * DI + h * HD + p]     = acc2[mi][ni][jj]     + Dh * x0;
                g_y[(size_t)(t0 + t + 8) * DI + h * HD + p] = acc2[mi][ni][2 + jj] + Dh * x1;
            }
        }
    }
}

// ------------------------------ K4: rmsnorm + gate --------------------------
__global__ void k_norm(const float* __restrict__ nw, const float* __restrict__ nb) {
    int t = blockIdx.x, tid = threadIdx.x;
    __shared__ float red[256];
    float ss = 0.f;
    for (int i = tid; i < DI; i += 256) {
        float v = g_y[(size_t)t * DI + i];
        ss += v * v;
    }
    red[tid] = ss;
    __syncthreads();
    for (int o = 128; o > 0; o >>= 1) {
        if (tid < o) red[tid] += red[tid + o];
        __syncthreads();
    }
    float inv = rsqrtf(red[0] / (float)DI + 1e-6f);
    for (int i = tid; i < DI; i += 256) {
        float v = g_y[(size_t)t * DI + i] * inv * nw[i] + nb[i];
        float z = g_zx[(size_t)t * DIPP + i];
        float o = v * silu(z);
        split_store(&g_yg_hi[(size_t)t * DI + i], &g_yg_lo[(size_t)t * DI + i], o);
    }
}

// ------------------------------ host ----------------------------------------
extern "C" void kernel_launch(void* const* d_in, const int* in_sizes, int n_in,
                              void* d_out, int out_size) {
    const float* u       = (const float*)d_in[0];
    const float* W_in    = (const float*)d_in[1];
    const float* conv_w  = (const float*)d_in[2];
    const float* conv_b  = (const float*)d_in[3];
    const float* W_out   = (const float*)d_in[4];
    const float* norm_w  = (const float*)d_in[5];
    const float* norm_b  = (const float*)d_in[6];
    const float* dt_bias = (const float*)d_in[7];
    const float* A_log   = (const float*)d_in[8];
    const float* Dp      = (const float*)d_in[9];
    float* out = (float*)d_out;

    void *p_ub, *p_wih, *p_wil, *p_woh, *p_wol, *p_zx, *p_ygh, *p_ygl;
    cudaGetSymbolAddress(&p_ub, g_ub);
    cudaGetSymbolAddress(&p_wih, g_Win_hi);
    cudaGetSymbolAddress(&p_wil, g_Win_lo);
    cudaGetSymbolAddress(&p_woh, g_Wout_hi);
    cudaGetSymbolAddress(&p_wol, g_Wout_lo);
    cudaGetSymbolAddress(&p_zx, g_zx);
    cudaGetSymbolAddress(&p_ygh, g_yg_hi);
    cudaGetSymbolAddress(&p_ygl, g_yg_lo);

    cudaFuncSetAttribute(gemm_kernel<false>,
                         cudaFuncAttributeMaxDynamicSharedMemorySize, GEMM_SMEM);
    cudaFuncSetAttribute(gemm_kernel<true>,
                         cudaFuncAttributeMaxDynamicSharedMemorySize, GEMM_SMEM);
    cudaFuncSetAttribute(k_out,
                         cudaFuncAttributeMaxDynamicSharedMemorySize, KOUT_SMEM);

    k_cvt_u<<<4096, 256>>>(u);
    k_split_win<<<(DIPP * DM + 255) / 256, 256>>>(W_in);
    k_split_wout<<<(DM * DI + 255) / 256, 256>>>(W_out);

    gemm_kernel<false><<<dim3(DIPP / 128, SEQ / 128), 256, GEMM_SMEM>>>(
        (const __nv_bfloat16*)p_ub, nullptr,
        (const __nv_bfloat16*)p_wih, (const __nv_bfloat16*)p_wil,
        (float*)p_zx, SEQ, DIPP, DM);

    k_conv<<<dim3(DCI / 256, SEQ / 64), 256>>>(conv_w, conv_b);
    k_dt<<<dim3(NC, NH), CH>>>(dt_bias, A_log);
    k_states<<<dim3(NC, NH), 256>>>();
    k_prop<<<(NH * HD * DS) / 256, 256>>>();
    k_out<<<dim3(NC, NH), 256, KOUT_SMEM>>>(Dp);
    k_norm<<<SEQ, 256>>>(norm_w, norm_b);

    gemm_kernel<true><<<dim3(DM / 128, SEQ / 128), 256, GEMM_SMEM>>>(
        (const __nv_bfloat16*)p_ygh, (const __nv_bfloat16*)p_ygl,
        (const __nv_bfloat16*)p_woh, (const __nv_bfloat16*)p_wol,
        out, SEQ, DM, DI);
}

// round 5
// speedup vs baseline: 1.3096x; 1.0106x over previous
#include <cuda_runtime.h>
#include <cuda_bf16.h>
#include <cstdint>
#include <cstddef>

// ---------------------------------------------------------------------------
// Mamba2 block forward, SEQ=4096, D_MODEL=1024.  (mma.sync everywhere;
// tcgen05 rejected by the harness toolchain target sm_100.)
//  K1/K5 : split-bf16 tensor-core GEMMs, now with ldmatrix.x4 fragments
//  K3a/K3c: scan kernels via split-bf16 mma (validated round 3)
// ---------------------------------------------------------------------------

#define SEQ   4096
#define DM    1024
#define DIP   4384
#define DIPP  4480
#define DI    2048
#define DCI   2304
#define NH    32
#define HD    64
#define DS    128
#define CH    128
#define NC    32

// ------------------------------ scratch ------------------------------------
__device__ __nv_bfloat16 g_ub[SEQ * DM];
__device__ __nv_bfloat16 g_Win_hi[DIPP * DM];
__device__ __nv_bfloat16 g_Win_lo[DIPP * DM];
__device__ __nv_bfloat16 g_Wout_hi[DM * DI];
__device__ __nv_bfloat16 g_Wout_lo[DM * DI];
__device__ float g_zx[(size_t)SEQ * DIPP];
__device__ float g_xc[(size_t)SEQ * DCI];
__device__ float g_dts[NC * NH * CH];
__device__ float g_cumS[NC * NH * CH];
__device__ float g_Sloc[(size_t)NC * NH * HD * DS];
__device__ float g_hinit[(size_t)NC * NH * HD * DS];
__device__ float g_y[(size_t)SEQ * DI];
__device__ __nv_bfloat16 g_yg_hi[(size_t)SEQ * DI];
__device__ __nv_bfloat16 g_yg_lo[(size_t)SEQ * DI];

// ------------------------------ helpers ------------------------------------
__device__ __forceinline__ uint32_t smem_u32(const void* p) {
    uint32_t a;
    asm("{ .reg .u64 t; cvta.to.shared.u64 t, %1; cvt.u32.u64 %0, t; }"
        : "=r"(a) : "l"(p));
    return a;
}
__device__ __forceinline__ void cp16s(uint32_t saddr, const void* g) {
    asm volatile("cp.async.cg.shared.global [%0], [%1], 16;\n" :: "r"(saddr), "l"(g));
}
__device__ __forceinline__ void cp16(void* smem, const void* gmem) {
    cp16s((uint32_t)__cvta_generic_to_shared(smem), gmem);
}
__device__ __forceinline__ void cp_commit() { asm volatile("cp.async.commit_group;\n"); }

__device__ __forceinline__ uint32_t lds32(const __nv_bfloat16* p) {
    return *reinterpret_cast<const uint32_t*>(p);
}
__device__ __forceinline__ void ldsm4(uint32_t* r, uint32_t addr) {
    asm volatile("ldmatrix.sync.aligned.m8n8.x4.shared.b16 {%0,%1,%2,%3}, [%4];"
        : "=r"(r[0]), "=r"(r[1]), "=r"(r[2]), "=r"(r[3]) : "r"(addr));
}
__device__ __forceinline__ void mma16816(float* d, const uint32_t* a, uint32_t b0, uint32_t b1) {
    asm volatile(
        "mma.sync.aligned.m16n8k16.row.col.f32.bf16.bf16.f32 "
        "{%0,%1,%2,%3}, {%4,%5,%6,%7}, {%8,%9}, {%0,%1,%2,%3};\n"
        : "+f"(d[0]), "+f"(d[1]), "+f"(d[2]), "+f"(d[3])
        : "r"(a[0]), "r"(a[1]), "r"(a[2]), "r"(a[3]), "r"(b0), "r"(b1));
}
__device__ __forceinline__ float silu(float x) { return x / (1.f + expf(-x)); }
__device__ __forceinline__ void split_store(__nv_bfloat16* hi, __nv_bfloat16* lo, float v) {
    __nv_bfloat16 h = __float2bfloat16(v);
    *hi = h;
    *lo = __float2bfloat16(v - __bfloat162float(h));
}

// ------------------------------ K0 -----------------------------------------
__global__ void k_cvt_u(const float* __restrict__ u) {
    for (int i = blockIdx.x * blockDim.x + threadIdx.x; i < SEQ * DM;
         i += gridDim.x * blockDim.x)
        g_ub[i] = __float2bfloat16(u[i]);
}
__global__ void k_split_win(const float* __restrict__ W) {
    int i = blockIdx.x * blockDim.x + threadIdx.x;
    if (i >= DIPP * DM) return;
    int r = i >> 10, c = i & 1023;
    float w = (r < DIP) ? W[r * DM + c] : 0.f;
    split_store(&g_Win_hi[i], &g_Win_lo[i], w);
}
__global__ void k_split_wout(const float* __restrict__ W) {
    int i = blockIdx.x * blockDim.x + threadIdx.x;
    if (i >= DM * DI) return;
    split_store(&g_Wout_hi[i], &g_Wout_lo[i], W[i]);
}

// ------------------------------ GEMM ---------------------------------------
// C[M,N] = (A0 (+A1)) @ (B0 + B1)^T, K-contiguous row-major operands.
// Tiles: BM=BN=128, BK=32, 256 threads, warps 4(m) x 2(n), warp tile 32x64.
// Fragments via ldmatrix.x4; B hi/lo loaded-then-consumed to limit registers.
#define TILEB 10240u                       // 128 rows x 40 bf16 x 2B

template <bool ALO>
__global__ __launch_bounds__(256, 2) void gemm_kernel(
    const __nv_bfloat16* __restrict__ A0p, const __nv_bfloat16* __restrict__ A1p,
    const __nv_bfloat16* __restrict__ B0p, const __nv_bfloat16* __restrict__ B1p,
    float* __restrict__ C, int M, int N, int K)
{
    extern __shared__ __nv_bfloat16 smb[];
    constexpr uint32_t SLOTS = ALO ? 4u : 3u;
    constexpr uint32_t STGB = SLOTS * TILEB;
    constexpr uint32_t A0S = 0;
    constexpr uint32_t A1S = TILEB;                    // ALO only
    constexpr uint32_t B0S = (ALO ? 2u : 1u) * TILEB;
    constexpr uint32_t B1S = (ALO ? 3u : 2u) * TILEB;

    const int tid = threadIdx.x;
    const int lane = tid & 31, wid = tid >> 5;
    const int g = lane >> 2, q = lane & 3;
    const int wm = wid & 3, wn = wid >> 2;
    const int bm = blockIdx.y * 128, bn = blockIdx.x * 128;
    const uint32_t sbase = smem_u32(smb);

    // ldmatrix per-lane offsets: row = base + (lane&15), k-half = (lane>>4)*8
    const int la = lane & 15;
    const uint32_t lk2 = (uint32_t)(lane >> 4) * 16;   // bytes
    const uint32_t aoff = (uint32_t)((wm * 32 + la) * 40) * 2 + lk2;
    const uint32_t boff = (uint32_t)((wn * 64 + la) * 40) * 2 + lk2;

    float acc[2][8][4];
#pragma unroll
    for (int a = 0; a < 2; a++)
#pragma unroll
        for (int b = 0; b < 8; b++)
#pragma unroll
            for (int c2 = 0; c2 < 4; c2++) acc[a][b][c2] = 0.f;

    const __nv_bfloat16* gA0 = A0p + (size_t)bm * K;
    const __nv_bfloat16* gA1 = ALO ? (A1p + (size_t)bm * K) : nullptr;
    const __nv_bfloat16* gB0 = B0p + (size_t)bn * K;
    const __nv_bfloat16* gB1 = B1p + (size_t)bn * K;

    auto load_stage = [&](int st, int k0) {
        uint32_t base = sbase + st * STGB;
#pragma unroll
        for (int i = 0; i < 2; i++) {
            int ch = tid + i * 256;
            int r = ch >> 2, cc = ch & 3;
            size_t go = (size_t)r * K + k0 + cc * 8;
            uint32_t so = (uint32_t)(r * 40 + cc * 8) * 2;
            cp16s(base + A0S + so, gA0 + go);
            if (ALO) cp16s(base + A1S + so, gA1 + go);
            cp16s(base + B0S + so, gB0 + go);
            cp16s(base + B1S + so, gB1 + go);
        }
        cp_commit();
    };

    load_stage(0, 0);
    const int KT = K >> 5;
    for (int kt = 0; kt < KT; kt++) {
        if (kt + 1 < KT) load_stage((kt + 1) & 1, (kt + 1) << 5);
        else cp_commit();
        asm volatile("cp.async.wait_group 1;\n");
        __syncthreads();
        const uint32_t stb = sbase + (kt & 1) * STGB;
#pragma unroll
        for (int ks = 0; ks < 2; ks++) {
            const uint32_t kb = (uint32_t)ks * 32;     // bytes (16 elems)
            uint32_t ah[2][4], al[2][4];
#pragma unroll
            for (int mi = 0; mi < 2; mi++)
                ldsm4(ah[mi], stb + A0S + aoff + (uint32_t)mi * 1280 + kb);
            if (ALO) {
#pragma unroll
                for (int mi = 0; mi < 2; mi++)
                    ldsm4(al[mi], stb + A1S + aoff + (uint32_t)mi * 1280 + kb);
            }
            uint32_t b[4][4];
#pragma unroll
            for (int n2 = 0; n2 < 4; n2++)
                ldsm4(b[n2], stb + B0S + boff + (uint32_t)n2 * 1280 + kb);
#pragma unroll
            for (int n2 = 0; n2 < 4; n2++)
#pragma unroll
                for (int mi = 0; mi < 2; mi++) {
                    mma16816(acc[mi][2 * n2],     ah[mi], b[n2][0], b[n2][2]);
                    mma16816(acc[mi][2 * n2 + 1], ah[mi], b[n2][1], b[n2][3]);
                    if (ALO) {
                        mma16816(acc[mi][2 * n2],     al[mi], b[n2][0], b[n2][2]);
                        mma16816(acc[mi][2 * n2 + 1], al[mi], b[n2][1], b[n2][3]);
                    }
                }
#pragma unroll
            for (int n2 = 0; n2 < 4; n2++)
                ldsm4(b[n2], stb + B1S + boff + (uint32_t)n2 * 1280 + kb);
#pragma unroll
            for (int n2 = 0; n2 < 4; n2++)
#pragma unroll
                for (int mi = 0; mi < 2; mi++) {
                    mma16816(acc[mi][2 * n2],     ah[mi], b[n2][0], b[n2][2]);
                    mma16816(acc[mi][2 * n2 + 1], ah[mi], b[n2][1], b[n2][3]);
                }
        }
        __syncthreads();
    }
#pragma unroll
    for (int mi = 0; mi < 2; mi++) {
        int r0 = bm + wm * 32 + mi * 16 + g;
#pragma unroll
        for (int ni = 0; ni < 8; ni++) {
            int cc = bn + wn * 64 + ni * 8 + 2 * q;
            float* p = C + (size_t)r0 * N + cc;
            p[0] = acc[mi][ni][0];
            p[1] = acc[mi][ni][1];
            p += 8 * (size_t)N;
            p[0] = acc[mi][ni][2];
            p[1] = acc[mi][ni][3];
        }
    }
}

// ------------------------------ K2: conv -----------------------------------
__global__ void k_conv(const float* __restrict__ cw, const float* __restrict__ cb) {
    int c = blockIdx.x * 256 + threadIdx.x;
    int t0 = blockIdx.y * 64;
    float w0 = cw[c * 4 + 0], w1 = cw[c * 4 + 1], w2 = cw[c * 4 + 2], w3 = cw[c * 4 + 3];
    float b = cb[c];
    const float* col = g_zx + DI + c;
    float v0 = (t0 >= 3) ? col[(size_t)(t0 - 3) * DIPP] : 0.f;
    float v1 = (t0 >= 2) ? col[(size_t)(t0 - 2) * DIPP] : 0.f;
    float v2 = (t0 >= 1) ? col[(size_t)(t0 - 1) * DIPP] : 0.f;
    for (int t = t0; t < t0 + 64; t++) {
        float v3 = col[(size_t)t * DIPP];
        float s = w0 * v0 + w1 * v1 + w2 * v2 + w3 * v3 + b;
        g_xc[(size_t)t * DCI + c] = silu(s);
        v0 = v1; v1 = v2; v2 = v3;
    }
}

// ------------------------------ K2b ----------------------------------------
__global__ void k_dt(const float* __restrict__ dt_bias, const float* __restrict__ A_log) {
    int c = blockIdx.x, h = blockIdx.y, t = threadIdx.x;
    __shared__ float s[CH];
    float raw = g_zx[(size_t)(c * CH + t) * DIPP + 4352 + h] + dt_bias[h];
    float dtsp = (raw > 20.f) ? raw : log1pf(expf(raw));
    float la = dtsp * (-expf(A_log[h]));
    s[t] = la;
    __syncthreads();
    for (int off = 1; off < CH; off <<= 1) {
        float v = (t >= off) ? s[t - off] : 0.f;
        __syncthreads();
        s[t] += v;
        __syncthreads();
    }
    int base = (c * NH + h) * CH;
    g_dts[base + t] = dtsp;
    g_cumS[base + t] = s[t];
}

// ------------------------------ K3a ----------------------------------------
__global__ __launch_bounds__(256) void k_states() {
    __shared__ __nv_bfloat16 XTh[64 * 36], XTl[64 * 36];
    __shared__ __nv_bfloat16 BTh[128 * 36], BTl[128 * 36];
    __shared__ float wv[128];
    int c = blockIdx.x, h = blockIdx.y, t0 = c * CH;
    int tid = threadIdx.x, lane = tid & 31, w = tid >> 5;
    int g = lane >> 2, q = lane & 3;
    int wr = w & 1, wc = w >> 1;
    int sb = (c * NH + h) * CH;
    if (tid < 128) {
        float Send = g_cumS[sb + CH - 1];
        wv[tid] = expf(Send - g_cumS[sb + tid]) * g_dts[sb + tid];
    }
    float acc[2][4][4] = {};
    for (int kt = 0; kt < 4; kt++) {
        __syncthreads();
#pragma unroll
        for (int i = 0; i < 8; i++) {
            int idx = tid + i * 256;
            int s = idx >> 6, p = idx & 63;
            float v = wv[kt * 32 + s] *
                      g_xc[(size_t)(t0 + kt * 32 + s) * DCI + h * HD + p];
            split_store(&XTh[p * 36 + s], &XTl[p * 36 + s], v);
        }
#pragma unroll
        for (int i = 0; i < 16; i++) {
            int idx = tid + i * 256;
            int s = idx >> 7, n = idx & 127;
            float v = g_xc[(size_t)(t0 + kt * 32 + s) * DCI + DI + n];
            split_store(&BTh[n * 36 + s], &BTl[n * 36 + s], v);
        }
        __syncthreads();
#pragma unroll
        for (int ks = 0; ks < 2; ks++) {
            int k0 = ks * 16 + 2 * q;
            uint32_t ah[2][4], al[2][4];
#pragma unroll
            for (int mi = 0; mi < 2; mi++) {
                const __nv_bfloat16* pa = XTh + (wr * 32 + mi * 16 + g) * 36 + k0;
                ah[mi][0] = lds32(pa);        ah[mi][1] = lds32(pa + 8 * 36);
                ah[mi][2] = lds32(pa + 8);    ah[mi][3] = lds32(pa + 8 * 36 + 8);
                const __nv_bfloat16* pl = XTl + (wr * 32 + mi * 16 + g) * 36 + k0;
                al[mi][0] = lds32(pl);        al[mi][1] = lds32(pl + 8 * 36);
                al[mi][2] = lds32(pl + 8);    al[mi][3] = lds32(pl + 8 * 36 + 8);
            }
#pragma unroll
            for (int ni = 0; ni < 4; ni++) {
                const __nv_bfloat16* pb = BTh + (wc * 32 + ni * 8 + g) * 36 + k0;
                uint32_t bh0 = lds32(pb), bh1 = lds32(pb + 8);
                const __nv_bfloat16* pbl = BTl + (wc * 32 + ni * 8 + g) * 36 + k0;
                uint32_t bl0 = lds32(pbl), bl1 = lds32(pbl + 8);
#pragma unroll
                for (int mi = 0; mi < 2; mi++) {
                    mma16816(acc[mi][ni], ah[mi], bh0, bh1);
                    mma16816(acc[mi][ni], ah[mi], bl0, bl1);
                    mma16816(acc[mi][ni], al[mi], bh0, bh1);
                }
            }
        }
    }
    size_t base = (size_t)(c * NH + h) * (HD * DS);
#pragma unroll
    for (int mi = 0; mi < 2; mi++) {
        int p0 = wr * 32 + mi * 16 + g;
#pragma unroll
        for (int ni = 0; ni < 4; ni++) {
            int n0 = wc * 32 + ni * 8 + 2 * q;
            g_Sloc[base + p0 * DS + n0]           = acc[mi][ni][0];
            g_Sloc[base + p0 * DS + n0 + 1]       = acc[mi][ni][1];
            g_Sloc[base + (p0 + 8) * DS + n0]     = acc[mi][ni][2];
            g_Sloc[base + (p0 + 8) * DS + n0 + 1] = acc[mi][ni][3];
        }
    }
}

// ------------------------------ K3b ----------------------------------------
__global__ void k_prop() {
    int idx = blockIdx.x * 256 + threadIdx.x;
    int h = idx >> 13;
    float hcur = 0.f;
    for (int c = 0; c < NC; c++) {
        size_t off = (size_t)c * (NH * HD * DS) + idx;
        g_hinit[off] = hcur;
        float tot = expf(g_cumS[(c * NH + h) * CH + CH - 1]);
        hcur = tot * hcur + g_Sloc[off];
    }
}

// ------------------------------ K3c ----------------------------------------
#define KO_ELEMS (2 * 17408 + 4 * 4608)
#define KOUT_SMEM (KO_ELEMS * 2 + 1024)
__global__ __launch_bounds__(256) void k_out(const float* __restrict__ Dp) {
    extern __shared__ __nv_bfloat16 smb[];
    __nv_bfloat16* Gh = smb;
    __nv_bfloat16* Gl = smb + 17408;
    __nv_bfloat16* Ah = smb + 34816;
    __nv_bfloat16* Al = smb + 39424;
    __nv_bfloat16* Bh = smb + 44032;
    __nv_bfloat16* Bl = smb + 48640;
    float* Sa = (float*)(smb + KO_ELEMS);
    float* Da = Sa + 128;

    int c = blockIdx.x, h = blockIdx.y, t0 = c * CH;
    int tid = threadIdx.x, lane = tid & 31, w = tid >> 5;
    int g = lane >> 2, q = lane & 3;
    int sb = (c * NH + h) * CH;
    if (tid < 128) {
        Sa[tid] = g_cumS[sb + tid];
        Da[tid] = g_dts[sb + tid];
    }

    {
        int wr = w & 3, wc = w >> 2;
        float acc[2][8][4] = {};
        for (int kt = 0; kt < 4; kt++) {
            __syncthreads();
#pragma unroll
            for (int i = 0; i < 16; i++) {
                int idx = tid + i * 256;
                int t = idx >> 5, n = idx & 31;
                size_t row = (size_t)(t0 + t) * DCI + DI + kt * 32 + n;
                split_store(&Ah[t * 36 + n], &Al[t * 36 + n], g_xc[row + DS]);
                split_store(&Bh[t * 36 + n], &Bl[t * 36 + n], g_xc[row]);
            }
            __syncthreads();
#pragma unroll
            for (int ks = 0; ks < 2; ks++) {
                int k0 = ks * 16 + 2 * q;
                uint32_t ah[2][4], al[2][4];
#pragma unroll
                for (int mi = 0; mi < 2; mi++) {
                    const __nv_bfloat16* pa = Ah + (wr * 32 + mi * 16 + g) * 36 + k0;
                    ah[mi][0] = lds32(pa);     ah[mi][1] = lds32(pa + 8 * 36);
                    ah[mi][2] = lds32(pa + 8); ah[mi][3] = lds32(pa + 8 * 36 + 8);
                    const __nv_bfloat16* pl = Al + (wr * 32 + mi * 16 + g) * 36 + k0;
                    al[mi][0] = lds32(pl);     al[mi][1] = lds32(pl + 8 * 36);
                    al[mi][2] = lds32(pl + 8); al[mi][3] = lds32(pl + 8 * 36 + 8);
                }
#pragma unroll
                for (int ni = 0; ni < 8; ni++) {
                    const __nv_bfloat16* pb = Bh + (wc * 64 + ni * 8 + g) * 36 + k0;
                    uint32_t bh0 = lds32(pb), bh1 = lds32(pb + 8);
                    const __nv_bfloat16* pbl = Bl + (wc * 64 + ni * 8 + g) * 36 + k0;
                    uint32_t bl0 = lds32(pbl), bl1 = lds32(pbl + 8);
#pragma unroll
                    for (int mi = 0; mi < 2; mi++) {
                        mma16816(acc[mi][ni], ah[mi], bh0, bh1);
                        mma16816(acc[mi][ni], ah[mi], bl0, bl1);
                        mma16816(acc[mi][ni], al[mi], bh0, bh1);
                    }
                }
            }
        }
#pragma unroll
        for (int mi = 0; mi < 2; mi++) {
            int tA = wr * 32 + mi * 16 + g;
            float SaA = Sa[tA], SaB = Sa[tA + 8];
#pragma unroll
            for (int ni = 0; ni < 8; ni++) {
                int s0 = wc * 64 + ni * 8 + 2 * q;
#pragma unroll
                for (int jj = 0; jj < 2; jj++) {
                    int s = s0 + jj;
                    float ds = Da[s], Ss = Sa[s];
                    float v0 = (s <= tA)     ? acc[mi][ni][jj]     * expf(SaA - Ss) * ds : 0.f;
                    float v1 = (s <= tA + 8) ? acc[mi][ni][2 + jj] * expf(SaB - Ss) * ds : 0.f;
                    split_store(&Gh[tA * 136 + s],       &Gl[tA * 136 + s],       v0);
                    split_store(&Gh[(tA + 8) * 136 + s], &Gl[(tA + 8) * 136 + s], v1);
                }
            }
        }
    }
    __syncthreads();

    int wr2 = w & 3, wc2 = w >> 2;
    float acc2[2][4][4] = {};
    for (int kt = 0; kt < 4; kt++) {
        if (kt) __syncthreads();
#pragma unroll
        for (int i = 0; i < 8; i++) {
            int idx = tid + i * 256;
            int s = idx >> 6, p = idx & 63;
            float v = g_xc[(size_t)(t0 + kt * 32 + s) * DCI + h * HD + p];
            split_store(&Bh[p * 36 + s], &Bl[p * 36 + s], v);
        }
        __syncthreads();
#pragma unroll
        for (int ks = 0; ks < 2; ks++) {
            int kg = kt * 32 + ks * 16 + 2 * q;
            int kb = ks * 16 + 2 * q;
            uint32_t ah[2][4], al[2][4];
#pragma unroll
            for (int mi = 0; mi < 2; mi++) {
                const __nv_bfloat16* pa = Gh + (wr2 * 32 + mi * 16 + g) * 136 + kg;
                ah[mi][0] = lds32(pa);     ah[mi][1] = lds32(pa + 8 * 136);
                ah[mi][2] = lds32(pa + 8); ah[mi][3] = lds32(pa + 8 * 136 + 8);
                const __nv_bfloat16* pl = Gl + (wr2 * 32 + mi * 16 + g) * 136 + kg;
                al[mi][0] = lds32(pl);     al[mi][1] = lds32(pl + 8 * 136);
                al[mi][2] = lds32(pl + 8); al[mi][3] = lds32(pl + 8 * 136 + 8);
            }
#pragma unroll
            for (int ni = 0; ni < 4; ni++) {
                const __nv_bfloat16* pb = Bh + (wc2 * 32 + ni * 8 + g) * 36 + kb;
                uint32_t bh0 = lds32(pb), bh1 = lds32(pb + 8);
                const __nv_bfloat16* pbl = Bl + (wc2 * 32 + ni * 8 + g) * 36 + kb;
                uint32_t bl0 = lds32(pbl), bl1 = lds32(pbl + 8);
#pragma unroll
                for (int mi = 0; mi < 2; mi++) {
                    mma16816(acc2[mi][ni], ah[mi], bh0, bh1);
                    mma16816(acc2[mi][ni], ah[mi], bl0, bl1);
                    mma16816(acc2[mi][ni], al[mi], bh0, bh1);
                }
            }
        }
    }
    for (int kt = 0; kt < 4; kt++) {
        __syncthreads();
#pragma unroll
        for (int i = 0; i < 16; i++) {
            int idx = tid + i * 256;
            int t = idx >> 5, n = idx & 31;
            float v = expf(Sa[t]) *
                      g_xc[(size_t)(t0 + t) * DCI + DI + DS + kt * 32 + n];
            split_store(&Ah[t * 36 + n], &Al[t * 36 + n], v);
        }
#pragma unroll
        for (int i = 0; i < 8; i++) {
            int idx = tid + i * 256;
            int p = idx >> 5, n = idx & 31;
            float v = g_hinit[(size_t)c * (NH * HD * DS) + h * (HD * DS) + p * DS + kt * 32 + n];
            split_store(&Bh[p * 36 + n], &Bl[p * 36 + n], v);
        }
        __syncthreads();
#pragma unroll
        for (int ks = 0; ks < 2; ks++) {
            int k0 = ks * 16 + 2 * q;
            uint32_t ah[2][4], al[2][4];
#pragma unroll
            for (int mi = 0; mi < 2; mi++) {
                const __nv_bfloat16* pa = Ah + (wr2 * 32 + mi * 16 + g) * 36 + k0;
                ah[mi][0] = lds32(pa);     ah[mi][1] = lds32(pa + 8 * 36);
                ah[mi][2] = lds32(pa + 8); ah[mi][3] = lds32(pa + 8 * 36 + 8);
                const __nv_bfloat16* pl = Al + (wr2 * 32 + mi * 16 + g) * 36 + k0;
                al[mi][0] = lds32(pl);     al[mi][1] = lds32(pl + 8 * 36);
                al[mi][2] = lds32(pl + 8); al[mi][3] = lds32(pl + 8 * 36 + 8);
            }
#pragma unroll
            for (int ni = 0; ni < 4; ni++) {
                const __nv_bfloat16* pb = Bh + (wc2 * 32 + ni * 8 + g) * 36 + k0;
                uint32_t bh0 = lds32(pb), bh1 = lds32(pb + 8);
                const __nv_bfloat16* pbl = Bl + (wc2 * 32 + ni * 8 + g) * 36 + k0;
                uint32_t bl0 = lds32(pbl), bl1 = lds32(pbl + 8);
#pragma unroll
                for (int mi = 0; mi < 2; mi++) {
                    mma16816(acc2[mi][ni], ah[mi], bh0, bh1);
                    mma16816(acc2[mi][ni], ah[mi], bl0, bl1);
                    mma16816(acc2[mi][ni], al[mi], bh0, bh1);
                }
            }
        }
    }
    float Dh = Dp[h];
#pragma unroll
    for (int mi = 0; mi < 2; mi++) {
        int t = wr2 * 32 + mi * 16 + g;
#pragma unroll
        for (int ni = 0; ni < 4; ni++) {
            int p0 = wc2 * 32 + ni * 8 + 2 * q;
#pragma unroll
            for (int jj = 0; jj < 2; jj++) {
                int p = p0 + jj;
                float x0 = g_xc[(size_t)(t0 + t) * DCI + h * HD + p];
                float x1 = g_xc[(size_t)(t0 + t + 8) * DCI + h * HD + p];
                g_y[(size_t)(t0 + t) * DI + h * HD + p]     = acc2[mi][ni][jj]     + Dh * x0;
                g_y[(size_t)(t0 + t + 8) * DI + h * HD + p] = acc2[mi][ni][2 + jj] + Dh * x1;
            }
        }
    }
}

// ------------------------------ K4 -----------------------------------------
__global__ void k_norm(const float* __restrict__ nw, const float* __restrict__ nb) {
    int t = blockIdx.x, tid = threadIdx.x;
    __shared__ float red[256];
    float ss = 0.f;
    for (int i = tid; i < DI; i += 256) {
        float v = g_y[(size_t)t * DI + i];
        ss += v * v;
    }
    red[tid] = ss;
    __syncthreads();
    for (int o = 128; o > 0; o >>= 1) {
        if (tid < o) red[tid] += red[tid + o];
        __syncthreads();
    }
    float inv = rsqrtf(red[0] / (float)DI + 1e-6f);
    for (int i = tid; i < DI; i += 256) {
        float v = g_y[(size_t)t * DI + i] * inv * nw[i] + nb[i];
        float z = g_zx[(size_t)t * DIPP + i];
        float o = v * silu(z);
        split_store(&g_yg_hi[(size_t)t * DI + i], &g_yg_lo[(size_t)t * DI + i], o);
    }
}

// ------------------------------ host ----------------------------------------
extern "C" void kernel_launch(void* const* d_in, const int* in_sizes, int n_in,
                              void* d_out, int out_size) {
    const float* u       = (const float*)d_in[0];
    const float* W_in    = (const float*)d_in[1];
    const float* conv_w  = (const float*)d_in[2];
    const float* conv_b  = (const float*)d_in[3];
    const float* W_out   = (const float*)d_in[4];
    const float* norm_w  = (const float*)d_in[5];
    const float* norm_b  = (const float*)d_in[6];
    const float* dt_bias = (const float*)d_in[7];
    const float* A_log   = (const float*)d_in[8];
    const float* Dp      = (const float*)d_in[9];
    float* out = (float*)d_out;

    void *p_ub, *p_wih, *p_wil, *p_woh, *p_wol, *p_zx, *p_ygh, *p_ygl;
    cudaGetSymbolAddress(&p_ub, g_ub);
    cudaGetSymbolAddress(&p_wih, g_Win_hi);
    cudaGetSymbolAddress(&p_wil, g_Win_lo);
    cudaGetSymbolAddress(&p_woh, g_Wout_hi);
    cudaGetSymbolAddress(&p_wol, g_Wout_lo);
    cudaGetSymbolAddress(&p_zx, g_zx);
    cudaGetSymbolAddress(&p_ygh, g_yg_hi);
    cudaGetSymbolAddress(&p_ygl, g_yg_lo);

    const uint32_t smem0 = 2 * 3 * TILEB;   // 61440
    const uint32_t smem1 = 2 * 4 * TILEB;   // 81920
    cudaFuncSetAttribute(gemm_kernel<false>,
                         cudaFuncAttributeMaxDynamicSharedMemorySize, smem0);
    cudaFuncSetAttribute(gemm_kernel<true>,
                         cudaFuncAttributeMaxDynamicSharedMemorySize, smem1);
    cudaFuncSetAttribute(k_out,
                         cudaFuncAttributeMaxDynamicSharedMemorySize, KOUT_SMEM);

    k_cvt_u<<<4096, 256>>>(u);
    k_split_win<<<(DIPP * DM + 255) / 256, 256>>>(W_in);
    k_split_wout<<<(DM * DI + 255) / 256, 256>>>(W_out);

    gemm_kernel<false><<<dim3(DIPP / 128, SEQ / 128), 256, smem0>>>(
        (const __nv_bfloat16*)p_ub, nullptr,
        (const __nv_bfloat16*)p_wih, (const __nv_bfloat16*)p_wil,
        (float*)p_zx, SEQ, DIPP, DM);

    k_conv<<<dim3(DCI / 256, SEQ / 64), 256>>>(conv_w, conv_b);
    k_dt<<<dim3(NC, NH), CH>>>(dt_bias, A_log);
    k_states<<<dim3(NC, NH), 256>>>();
    k_prop<<<(NH * HD * DS) / 256, 256>>>();
    k_out<<<dim3(NC, NH), 256, KOUT_SMEM>>>(Dp);
    k_norm<<<SEQ, 256>>>(norm_w, norm_b);

    gemm_kernel<true><<<dim3(DM / 128, SEQ / 128), 256, smem1>>>(
        (const __nv_bfloat16*)p_ygh, (const __nv_bfloat16*)p_ygl,
        (const __nv_bfloat16*)p_woh, (const __nv_bfloat16*)p_wol,
        out, SEQ, DM, DI);
}

// round 8
// speedup vs baseline: 1.4308x; 1.0925x over previous
#include <cuda_runtime.h>
#include <cuda_bf16.h>
#include <cstdint>
#include <cstddef>

// ---------------------------------------------------------------------------
// Mamba2 block forward, SEQ=4096, D_MODEL=1024.  mma.sync path (tcgen05 is
// blocked by the harness toolchain target sm_100).
//  R8 == R7 resubmission (infra failure, kernel validated by audit):
//  NST-stage gemm pipeline (correct wait->sync->compute->sync order),
//  shared per-chunk Graw kernel, __expf, bf16 hi/lo conv outputs.
// ---------------------------------------------------------------------------

#define SEQ   4096
#define DM    1024
#define DIP   4384
#define DIPP  4480
#define DI    2048
#define DCI   2304
#define NH    32
#define HD    64
#define DS    128
#define CH    128
#define NC    32

// ------------------------------ scratch ------------------------------------
__device__ __nv_bfloat16 g_ub[SEQ * DM];
__device__ __nv_bfloat16 g_Win_hi[DIPP * DM];
__device__ __nv_bfloat16 g_Win_lo[DIPP * DM];
__device__ __nv_bfloat16 g_Wout_hi[DM * DI];
__device__ __nv_bfloat16 g_Wout_lo[DM * DI];
__device__ float g_zx[(size_t)SEQ * DIPP];
__device__ float g_xc[(size_t)SEQ * DCI];
__device__ __nv_bfloat16 g_xh[(size_t)SEQ * DI];   // x hi
__device__ __nv_bfloat16 g_xl[(size_t)SEQ * DI];   // x lo
__device__ __nv_bfloat16 g_bch[SEQ * 256];         // B,C hi (cols 0..127=B, 128..255=C)
__device__ __nv_bfloat16 g_bcl[SEQ * 256];         // B,C lo
__device__ float g_dts[NC * NH * CH];
__device__ float g_cumS[NC * NH * CH];
__device__ float g_graw[(size_t)NC * CH * CH];     // raw C.B^T per chunk
__device__ float g_Sloc[(size_t)NC * NH * HD * DS];
__device__ float g_hinit[(size_t)NC * NH * HD * DS];
__device__ float g_y[(size_t)SEQ * DI];
__device__ __nv_bfloat16 g_yg_hi[(size_t)SEQ * DI];
__device__ __nv_bfloat16 g_yg_lo[(size_t)SEQ * DI];

// ------------------------------ helpers ------------------------------------
__device__ __forceinline__ uint32_t smem_u32(const void* p) {
    uint32_t a;
    asm("{ .reg .u64 t; cvta.to.shared.u64 t, %1; cvt.u32.u64 %0, t; }"
        : "=r"(a) : "l"(p));
    return a;
}
__device__ __forceinline__ void cp16s(uint32_t saddr, const void* g) {
    asm volatile("cp.async.cg.shared.global [%0], [%1], 16;\n" :: "r"(saddr), "l"(g));
}
__device__ __forceinline__ void cp_commit() { asm volatile("cp.async.commit_group;\n"); }

__device__ __forceinline__ uint32_t lds32(const __nv_bfloat16* p) {
    return *reinterpret_cast<const uint32_t*>(p);
}
__device__ __forceinline__ void ldsm4(uint32_t* r, uint32_t addr) {
    asm volatile("ldmatrix.sync.aligned.m8n8.x4.shared.b16 {%0,%1,%2,%3}, [%4];"
        : "=r"(r[0]), "=r"(r[1]), "=r"(r[2]), "=r"(r[3]) : "r"(addr));
}
__device__ __forceinline__ void mma16816(float* d, const uint32_t* a, uint32_t b0, uint32_t b1) {
    asm volatile(
        "mma.sync.aligned.m16n8k16.row.col.f32.bf16.bf16.f32 "
        "{%0,%1,%2,%3}, {%4,%5,%6,%7}, {%8,%9}, {%0,%1,%2,%3};\n"
        : "+f"(d[0]), "+f"(d[1]), "+f"(d[2]), "+f"(d[3])
        : "r"(a[0]), "r"(a[1]), "r"(a[2]), "r"(a[3]), "r"(b0), "r"(b1));
}
__device__ __forceinline__ float silu(float x) { return x / (1.f + __expf(-x)); }
__device__ __forceinline__ void split_store(__nv_bfloat16* hi, __nv_bfloat16* lo, float v) {
    __nv_bfloat16 h = __float2bfloat16(v);
    *hi = h;
    *lo = __float2bfloat16(v - __bfloat162float(h));
}

// ------------------------------ K0 -----------------------------------------
__global__ void k_cvt_u(const float* __restrict__ u) {
    for (int i = blockIdx.x * blockDim.x + threadIdx.x; i < SEQ * DM;
         i += gridDim.x * blockDim.x)
        g_ub[i] = __float2bfloat16(u[i]);
}
__global__ void k_split_win(const float* __restrict__ W) {
    int i = blockIdx.x * blockDim.x + threadIdx.x;
    if (i >= DIPP * DM) return;
    int r = i >> 10, c = i & 1023;
    float w = (r < DIP) ? W[r * DM + c] : 0.f;
    split_store(&g_Win_hi[i], &g_Win_lo[i], w);
}
__global__ void k_split_wout(const float* __restrict__ W) {
    int i = blockIdx.x * blockDim.x + threadIdx.x;
    if (i >= DM * DI) return;
    split_store(&g_Wout_hi[i], &g_Wout_lo[i], W[i]);
}

// ------------------------------ GEMM ---------------------------------------
// C[M,N] = (A0 (+A1)) @ (B0 + B1)^T, K-contiguous row-major operands.
// BM=BN=128, BK=32, 256 threads; ldmatrix.x4 fragments; NST-stage cp.async
// pipeline: load(kt+NST-1) -> wait(NST-1) -> sync -> compute(kt) -> sync.
#define TILEB 10240u                       // 128 rows x 40 bf16 x 2B

template <bool ALO, int NST>
__global__ __launch_bounds__(256, 2) void gemm_kernel(
    const __nv_bfloat16* __restrict__ A0p, const __nv_bfloat16* __restrict__ A1p,
    const __nv_bfloat16* __restrict__ B0p, const __nv_bfloat16* __restrict__ B1p,
    float* __restrict__ C, int M, int N, int K)
{
    extern __shared__ __nv_bfloat16 smb[];
    constexpr uint32_t SLOTS = ALO ? 4u : 3u;
    constexpr uint32_t STGB = SLOTS * TILEB;
    constexpr uint32_t A0S = 0;
    constexpr uint32_t A1S = TILEB;
    constexpr uint32_t B0S = (ALO ? 2u : 1u) * TILEB;
    constexpr uint32_t B1S = (ALO ? 3u : 2u) * TILEB;

    const int tid = threadIdx.x;
    const int lane = tid & 31, wid = tid >> 5;
    const int g = lane >> 2, q = lane & 3;
    const int wm = wid & 3, wn = wid >> 2;
    const int bm = blockIdx.y * 128, bn = blockIdx.x * 128;
    const uint32_t sbase = smem_u32(smb);

    const int la = lane & 15;
    const uint32_t lk2 = (uint32_t)(lane >> 4) * 16;
    const uint32_t aoff = (uint32_t)((wm * 32 + la) * 40) * 2 + lk2;
    const uint32_t boff = (uint32_t)((wn * 64 + la) * 40) * 2 + lk2;

    float acc[2][8][4];
#pragma unroll
    for (int a = 0; a < 2; a++)
#pragma unroll
        for (int b = 0; b < 8; b++)
#pragma unroll
            for (int c2 = 0; c2 < 4; c2++) acc[a][b][c2] = 0.f;

    const __nv_bfloat16* gA0 = A0p + (size_t)bm * K;
    const __nv_bfloat16* gA1 = ALO ? (A1p + (size_t)bm * K) : nullptr;
    const __nv_bfloat16* gB0 = B0p + (size_t)bn * K;
    const __nv_bfloat16* gB1 = B1p + (size_t)bn * K;

    auto load_stage = [&](int st, int k0) {
        uint32_t base = sbase + (uint32_t)st * STGB;
#pragma unroll
        for (int i = 0; i < 2; i++) {
            int ch = tid + i * 256;
            int r = ch >> 2, cc = ch & 3;
            size_t go = (size_t)r * K + k0 + cc * 8;
            uint32_t so = (uint32_t)(r * 40 + cc * 8) * 2;
            cp16s(base + A0S + so, gA0 + go);
            if (ALO) cp16s(base + A1S + so, gA1 + go);
            cp16s(base + B0S + so, gB0 + go);
            cp16s(base + B1S + so, gB1 + go);
        }
        cp_commit();
    };

#pragma unroll
    for (int p = 0; p < NST - 1; p++) load_stage(p, p << 5);

    const int KT = K >> 5;
    for (int kt = 0; kt < KT; kt++) {
        if (kt + NST - 1 < KT) load_stage((kt + NST - 1) % NST, (kt + NST - 1) << 5);
        else cp_commit();
        asm volatile("cp.async.wait_group %0;\n" :: "n"(NST - 1));
        __syncthreads();
        const uint32_t stb = sbase + (uint32_t)(kt % NST) * STGB;
#pragma unroll
        for (int ks = 0; ks < 2; ks++) {
            const uint32_t kb = (uint32_t)ks * 32;
            uint32_t ah[2][4], al[2][4];
#pragma unroll
            for (int mi = 0; mi < 2; mi++)
                ldsm4(ah[mi], stb + A0S + aoff + (uint32_t)mi * 1280 + kb);
            if (ALO) {
#pragma unroll
                for (int mi = 0; mi < 2; mi++)
                    ldsm4(al[mi], stb + A1S + aoff + (uint32_t)mi * 1280 + kb);
            }
            uint32_t b[4][4];
#pragma unroll
            for (int n2 = 0; n2 < 4; n2++)
                ldsm4(b[n2], stb + B0S + boff + (uint32_t)n2 * 1280 + kb);
#pragma unroll
            for (int n2 = 0; n2 < 4; n2++)
#pragma unroll
                for (int mi = 0; mi < 2; mi++) {
                    mma16816(acc[mi][2 * n2],     ah[mi], b[n2][0], b[n2][2]);
                    mma16816(acc[mi][2 * n2 + 1], ah[mi], b[n2][1], b[n2][3]);
                    if (ALO) {
                        mma16816(acc[mi][2 * n2],     al[mi], b[n2][0], b[n2][2]);
                        mma16816(acc[mi][2 * n2 + 1], al[mi], b[n2][1], b[n2][3]);
                    }
                }
#pragma unroll
            for (int n2 = 0; n2 < 4; n2++)
                ldsm4(b[n2], stb + B1S + boff + (uint32_t)n2 * 1280 + kb);
#pragma unroll
            for (int n2 = 0; n2 < 4; n2++)
#pragma unroll
                for (int mi = 0; mi < 2; mi++) {
                    mma16816(acc[mi][2 * n2],     ah[mi], b[n2][0], b[n2][2]);
                    mma16816(acc[mi][2 * n2 + 1], ah[mi], b[n2][1], b[n2][3]);
                }
        }
        __syncthreads();
    }
#pragma unroll
    for (int mi = 0; mi < 2; mi++) {
        int r0 = bm + wm * 32 + mi * 16 + g;
#pragma unroll
        for (int ni = 0; ni < 8; ni++) {
            int cc = bn + wn * 64 + ni * 8 + 2 * q;
            float* p = C + (size_t)r0 * N + cc;
            p[0] = acc[mi][ni][0];
            p[1] = acc[mi][ni][1];
            p += 8 * (size_t)N;
            p[0] = acc[mi][ni][2];
            p[1] = acc[mi][ni][3];
        }
    }
}

// ------------------------------ K2: conv (+ bf16 hi/lo outputs) -------------
__global__ void k_conv(const float* __restrict__ cw, const float* __restrict__ cb) {
    int c = blockIdx.x * 256 + threadIdx.x;
    int t0 = blockIdx.y * 64;
    float w0 = cw[c * 4 + 0], w1 = cw[c * 4 + 1], w2 = cw[c * 4 + 2], w3 = cw[c * 4 + 3];
    float b = cb[c];
    const float* col = g_zx + DI + c;
    float v0 = (t0 >= 3) ? col[(size_t)(t0 - 3) * DIPP] : 0.f;
    float v1 = (t0 >= 2) ? col[(size_t)(t0 - 2) * DIPP] : 0.f;
    float v2 = (t0 >= 1) ? col[(size_t)(t0 - 1) * DIPP] : 0.f;
    for (int t = t0; t < t0 + 64; t++) {
        float v3 = col[(size_t)t * DIPP];
        float s = w0 * v0 + w1 * v1 + w2 * v2 + w3 * v3 + b;
        float sv = silu(s);
        g_xc[(size_t)t * DCI + c] = sv;
        if (c < DI)
            split_store(&g_xh[(size_t)t * DI + c], &g_xl[(size_t)t * DI + c], sv);
        else
            split_store(&g_bch[t * 256 + c - DI], &g_bcl[t * 256 + c - DI], sv);
        v0 = v1; v1 = v2; v2 = v3;
    }
}

// ------------------------------ K2b ----------------------------------------
__global__ void k_dt(const float* __restrict__ dt_bias, const float* __restrict__ A_log) {
    int c = blockIdx.x, h = blockIdx.y, t = threadIdx.x;
    __shared__ float s[CH];
    float raw = g_zx[(size_t)(c * CH + t) * DIPP + 4352 + h] + dt_bias[h];
    float dtsp = (raw > 20.f) ? raw : log1pf(__expf(raw));
    float la = dtsp * (-__expf(A_log[h]));
    s[t] = la;
    __syncthreads();
    for (int off = 1; off < CH; off <<= 1) {
        float v = (t >= off) ? s[t - off] : 0.f;
        __syncthreads();
        s[t] += v;
        __syncthreads();
    }
    int base = (c * NH + h) * CH;
    g_dts[base + t] = dtsp;
    g_cumS[base + t] = s[t];
}

// ------------------------------ K_graw: raw G = C.B^T per chunk -------------
__global__ __launch_bounds__(256) void k_graw() {
    __shared__ __nv_bfloat16 Ah[128 * 36], Al[128 * 36], Bh[128 * 36], Bl[128 * 36];
    int c = blockIdx.x, t0 = c * CH;
    int tid = threadIdx.x, lane = tid & 31, w = tid >> 5;
    int g = lane >> 2, q = lane & 3;
    int wr = w & 3, wc = w >> 2;
    float acc[2][8][4] = {};
    for (int kt = 0; kt < 4; kt++) {
        if (kt) __syncthreads();
#pragma unroll
        for (int i = 0; i < 8; i++) {
            int idx = tid + i * 256;
            int t = idx >> 4, j = idx & 15;
            const uint32_t* sh = (const uint32_t*)g_bch + (size_t)(t0 + t) * 128 + kt * 16;
            const uint32_t* sl = (const uint32_t*)g_bcl + (size_t)(t0 + t) * 128 + kt * 16;
            ((uint32_t*)Ah)[t * 18 + j] = sh[64 + j];     // C
            ((uint32_t*)Al)[t * 18 + j] = sl[64 + j];
            ((uint32_t*)Bh)[t * 18 + j] = sh[j];          // B
            ((uint32_t*)Bl)[t * 18 + j] = sl[j];
        }
        __syncthreads();
#pragma unroll
        for (int ks = 0; ks < 2; ks++) {
            int k0 = ks * 16 + 2 * q;
            uint32_t ah[2][4], al[2][4];
#pragma unroll
            for (int mi = 0; mi < 2; mi++) {
                const __nv_bfloat16* pa = Ah + (wr * 32 + mi * 16 + g) * 36 + k0;
                ah[mi][0] = lds32(pa);     ah[mi][1] = lds32(pa + 8 * 36);
                ah[mi][2] = lds32(pa + 8); ah[mi][3] = lds32(pa + 8 * 36 + 8);
                const __nv_bfloat16* pl = Al + (wr * 32 + mi * 16 + g) * 36 + k0;
                al[mi][0] = lds32(pl);     al[mi][1] = lds32(pl + 8 * 36);
                al[mi][2] = lds32(pl + 8); al[mi][3] = lds32(pl + 8 * 36 + 8);
            }
#pragma unroll
            for (int ni = 0; ni < 8; ni++) {
                const __nv_bfloat16* pb = Bh + (wc * 64 + ni * 8 + g) * 36 + k0;
                uint32_t bh0 = lds32(pb), bh1 = lds32(pb + 8);
                const __nv_bfloat16* pbl = Bl + (wc * 64 + ni * 8 + g) * 36 + k0;
                uint32_t bl0 = lds32(pbl), bl1 = lds32(pbl + 8);
#pragma unroll
                for (int mi = 0; mi < 2; mi++) {
                    mma16816(acc[mi][ni], ah[mi], bh0, bh1);
                    mma16816(acc[mi][ni], ah[mi], bl0, bl1);
                    mma16816(acc[mi][ni], al[mi], bh0, bh1);
                }
            }
        }
    }
    float* dst = g_graw + (size_t)c * CH * CH;
#pragma unroll
    for (int mi = 0; mi < 2; mi++) {
        int t = wr * 32 + mi * 16 + g;
#pragma unroll
        for (int ni = 0; ni < 8; ni++) {
            int s0 = wc * 64 + ni * 8 + 2 * q;
            dst[t * CH + s0]           = acc[mi][ni][0];
            dst[t * CH + s0 + 1]       = acc[mi][ni][1];
            dst[(t + 8) * CH + s0]     = acc[mi][ni][2];
            dst[(t + 8) * CH + s0 + 1] = acc[mi][ni][3];
        }
    }
}

// ------------------------------ K3a: local states ---------------------------
__global__ __launch_bounds__(256) void k_states() {
    __shared__ __nv_bfloat16 XTh[64 * 36], XTl[64 * 36];
    __shared__ __nv_bfloat16 BTh[128 * 36], BTl[128 * 36];
    __shared__ float wv[128];
    int c = blockIdx.x, h = blockIdx.y, t0 = c * CH;
    int tid = threadIdx.x, lane = tid & 31, w = tid >> 5;
    int g = lane >> 2, q = lane & 3;
    int wr = w & 1, wc = w >> 1;
    int sb = (c * NH + h) * CH;
    if (tid < 128) {
        float Send = g_cumS[sb + CH - 1];
        wv[tid] = __expf(Send - g_cumS[sb + tid]) * g_dts[sb + tid];
    }
    float acc[2][4][4] = {};
    for (int kt = 0; kt < 4; kt++) {
        __syncthreads();
#pragma unroll
        for (int i = 0; i < 8; i++) {
            int idx = tid + i * 256;
            int s = idx >> 6, p = idx & 63;
            float v = wv[kt * 32 + s] *
                      g_xc[(size_t)(t0 + kt * 32 + s) * DCI + h * HD + p];
            split_store(&XTh[p * 36 + s], &XTl[p * 36 + s], v);
        }
#pragma unroll
        for (int i = 0; i < 16; i++) {
            int idx = tid + i * 256;
            int s = idx >> 7, n = idx & 127;
            int row = (t0 + kt * 32 + s) * 256 + n;
            BTh[n * 36 + s] = g_bch[row];
            BTl[n * 36 + s] = g_bcl[row];
        }
        __syncthreads();
#pragma unroll
        for (int ks = 0; ks < 2; ks++) {
            int k0 = ks * 16 + 2 * q;
            uint32_t ah[2][4], al[2][4];
#pragma unroll
            for (int mi = 0; mi < 2; mi++) {
                const __nv_bfloat16* pa = XTh + (wr * 32 + mi * 16 + g) * 36 + k0;
                ah[mi][0] = lds32(pa);        ah[mi][1] = lds32(pa + 8 * 36);
                ah[mi][2] = lds32(pa + 8);    ah[mi][3] = lds32(pa + 8 * 36 + 8);
                const __nv_bfloat16* pl = XTl + (wr * 32 + mi * 16 + g) * 36 + k0;
                al[mi][0] = lds32(pl);        al[mi][1] = lds32(pl + 8 * 36);
                al[mi][2] = lds32(pl + 8);    al[mi][3] = lds32(pl + 8 * 36 + 8);
            }
#pragma unroll
            for (int ni = 0; ni < 4; ni++) {
                const __nv_bfloat16* pb = BTh + (wc * 32 + ni * 8 + g) * 36 + k0;
                uint32_t bh0 = lds32(pb), bh1 = lds32(pb + 8);
                const __nv_bfloat16* pbl = BTl + (wc * 32 + ni * 8 + g) * 36 + k0;
                uint32_t bl0 = lds32(pbl), bl1 = lds32(pbl + 8);
#pragma unroll
                for (int mi = 0; mi < 2; mi++) {
                    mma16816(acc[mi][ni], ah[mi], bh0, bh1);
                    mma16816(acc[mi][ni], ah[mi], bl0, bl1);
                    mma16816(acc[mi][ni], al[mi], bh0, bh1);
                }
            }
        }
    }
    size_t base = (size_t)(c * NH + h) * (HD * DS);
#pragma unroll
    for (int mi = 0; mi < 2; mi++) {
        int p0 = wr * 32 + mi * 16 + g;
#pragma unroll
        for (int ni = 0; ni < 4; ni++) {
            int n0 = wc * 32 + ni * 8 + 2 * q;
            g_Sloc[base + p0 * DS + n0]           = acc[mi][ni][0];
            g_Sloc[base + p0 * DS + n0 + 1]       = acc[mi][ni][1];
            g_Sloc[base + (p0 + 8) * DS + n0]     = acc[mi][ni][2];
            g_Sloc[base + (p0 + 8) * DS + n0 + 1] = acc[mi][ni][3];
        }
    }
}

// ------------------------------ K3b ----------------------------------------
__global__ void k_prop() {
    int idx = blockIdx.x * 256 + threadIdx.x;
    int h = idx >> 13;
    float hcur = 0.f;
    for (int c = 0; c < NC; c++) {
        size_t off = (size_t)c * (NH * HD * DS) + idx;
        g_hinit[off] = hcur;
        float tot = __expf(g_cumS[(c * NH + h) * CH + CH - 1]);
        hcur = tot * hcur + g_Sloc[off];
    }
}

// ------------------------------ K3c: per-(chunk,head) outputs ---------------
#define KO_ELEMS (2 * 17408 + 4 * 4608)
#define KOUT_SMEM (KO_ELEMS * 2 + 2048)
__global__ __launch_bounds__(256) void k_out(const float* __restrict__ Dp) {
    extern __shared__ __nv_bfloat16 smb[];
    __nv_bfloat16* Gh = smb;
    __nv_bfloat16* Gl = smb + 17408;
    __nv_bfloat16* Ah = smb + 34816;
    __nv_bfloat16* Al = smb + 39424;
    __nv_bfloat16* Bh = smb + 44032;
    __nv_bfloat16* Bl = smb + 48640;
    float* Sa = (float*)(smb + KO_ELEMS);
    float* Da = Sa + 128;
    float* Ea = Da + 128;

    int c = blockIdx.x, h = blockIdx.y, t0 = c * CH;
    int tid = threadIdx.x, lane = tid & 31, w = tid >> 5;
    int g = lane >> 2, q = lane & 3;
    int sb = (c * NH + h) * CH;
    if (tid < 128) {
        float sv = g_cumS[sb + tid];
        Sa[tid] = sv;
        Da[tid] = g_dts[sb + tid];
        Ea[tid] = __expf(sv);
    }
    __syncthreads();

    // ---- stage G: mask + decay applied to precomputed raw C.B^T ----
    {
        const float* graw = g_graw + (size_t)c * CH * CH;
#pragma unroll
        for (int i = 0; i < 16; i++) {
            int idx = tid + i * 256;
            int t = idx >> 5, s4 = (idx & 31) * 4;
            float4 gr = *reinterpret_cast<const float4*>(graw + t * CH + s4);
            float St = Sa[t];
            float vv[4] = {gr.x, gr.y, gr.z, gr.w};
#pragma unroll
            for (int j = 0; j < 4; j++) {
                int s = s4 + j;
                float v = (s <= t) ? vv[j] * __expf(St - Sa[s]) * Da[s] : 0.f;
                split_store(&Gh[t * 136 + s], &Gl[t * 136 + s], v);
            }
        }
    }
    __syncthreads();

    int wr2 = w & 3, wc2 = w >> 2;
    float acc2[2][4][4] = {};

    // ---- term 2 first: acc2 = C @ h0^T (raw C; exp factored out) ----
    for (int kt = 0; kt < 4; kt++) {
        if (kt) __syncthreads();
#pragma unroll
        for (int i = 0; i < 8; i++) {           // C tile u32 copies
            int idx = tid + i * 256;
            int t = idx >> 4, j = idx & 15;
            const uint32_t* sh = (const uint32_t*)g_bch + (size_t)(t0 + t) * 128 + 64 + kt * 16;
            const uint32_t* sl = (const uint32_t*)g_bcl + (size_t)(t0 + t) * 128 + 64 + kt * 16;
            ((uint32_t*)Ah)[t * 18 + j] = sh[j];
            ((uint32_t*)Al)[t * 18 + j] = sl[j];
        }
#pragma unroll
        for (int i = 0; i < 8; i++) {           // h0 split staging
            int idx = tid + i * 256;
            int p = idx >> 5, n = idx & 31;
            float v = g_hinit[(size_t)c * (NH * HD * DS) + h * (HD * DS) + p * DS + kt * 32 + n];
            split_store(&Bh[p * 36 + n], &Bl[p * 36 + n], v);
        }
        __syncthreads();
#pragma unroll
        for (int ks = 0; ks < 2; ks++) {
            int k0 = ks * 16 + 2 * q;
            uint32_t ah[2][4], al[2][4];
#pragma unroll
            for (int mi = 0; mi < 2; mi++) {
                const __nv_bfloat16* pa = Ah + (wr2 * 32 + mi * 16 + g) * 36 + k0;
                ah[mi][0] = lds32(pa);     ah[mi][1] = lds32(pa + 8 * 36);
                ah[mi][2] = lds32(pa + 8); ah[mi][3] = lds32(pa + 8 * 36 + 8);
                const __nv_bfloat16* pl = Al + (wr2 * 32 + mi * 16 + g) * 36 + k0;
                al[mi][0] = lds32(pl);     al[mi][1] = lds32(pl + 8 * 36);
                al[mi][2] = lds32(pl + 8); al[mi][3] = lds32(pl + 8 * 36 + 8);
            }
#pragma unroll
            for (int ni = 0; ni < 4; ni++) {
                const __nv_bfloat16* pb = Bh + (wc2 * 32 + ni * 8 + g) * 36 + k0;
                uint32_t bh0 = lds32(pb), bh1 = lds32(pb + 8);
                const __nv_bfloat16* pbl = Bl + (wc2 * 32 + ni * 8 + g) * 36 + k0;
                uint32_t bl0 = lds32(pbl), bl1 = lds32(pbl + 8);
#pragma unroll
                for (int mi = 0; mi < 2; mi++) {
                    mma16816(acc2[mi][ni], ah[mi], bh0, bh1);
                    mma16816(acc2[mi][ni], ah[mi], bl0, bl1);
                    mma16816(acc2[mi][ni], al[mi], bh0, bh1);
                }
            }
        }
    }
    // scale term-2 accumulator by exp(Sa[t]) (row factor)
#pragma unroll
    for (int mi = 0; mi < 2; mi++) {
        int t = wr2 * 32 + mi * 16 + g;
        float e0 = Ea[t], e1 = Ea[t + 8];
#pragma unroll
        for (int ni = 0; ni < 4; ni++) {
            acc2[mi][ni][0] *= e0;
            acc2[mi][ni][1] *= e0;
            acc2[mi][ni][2] *= e1;
            acc2[mi][ni][3] *= e1;
        }
    }

    // ---- term 1: acc2 += G @ X^T ----
    for (int kt = 0; kt < 4; kt++) {
        __syncthreads();
#pragma unroll
        for (int i = 0; i < 8; i++) {
            int idx = tid + i * 256;
            int s = idx >> 6, p = idx & 63;
            size_t row = (size_t)(t0 + kt * 32 + s) * DI + h * HD + p;
            Bh[p * 36 + s] = g_xh[row];
            Bl[p * 36 + s] = g_xl[row];
        }
        __syncthreads();
#pragma unroll
        for (int ks = 0; ks < 2; ks++) {
            int kg = kt * 32 + ks * 16 + 2 * q;
            int kb = ks * 16 + 2 * q;
            uint32_t ah[2][4], al[2][4];
#pragma unroll
            for (int mi = 0; mi < 2; mi++) {
                const __nv_bfloat16* pa = Gh + (wr2 * 32 + mi * 16 + g) * 136 + kg;
                ah[mi][0] = lds32(pa);     ah[mi][1] = lds32(pa + 8 * 136);
                ah[mi][2] = lds32(pa + 8); ah[mi][3] = lds32(pa + 8 * 136 + 8);
                const __nv_bfloat16* pl = Gl + (wr2 * 32 + mi * 16 + g) * 136 + kg;
                al[mi][0] = lds32(pl);     al[mi][1] = lds32(pl + 8 * 136);
                al[mi][2] = lds32(pl + 8); al[mi][3] = lds32(pl + 8 * 136 + 8);
            }
#pragma unroll
            for (int ni = 0; ni < 4; ni++) {
                const __nv_bfloat16* pb = Bh + (wc2 * 32 + ni * 8 + g) * 36 + kb;
                uint32_t bh0 = lds32(pb), bh1 = lds32(pb + 8);
                const __nv_bfloat16* pbl = Bl + (wc2 * 32 + ni * 8 + g) * 36 + kb;
                uint32_t bl0 = lds32(pbl), bl1 = lds32(pbl + 8);
#pragma unroll
                for (int mi = 0; mi < 2; mi++) {
                    mma16816(acc2[mi][ni], ah[mi], bh0, bh1);
                    mma16816(acc2[mi][ni], ah[mi], bl0, bl1);
                    mma16816(acc2[mi][ni], al[mi], bh0, bh1);
                }
            }
        }
    }

    float Dh = Dp[h];
#pragma unroll
    for (int mi = 0; mi < 2; mi++) {
        int t = wr2 * 32 + mi * 16 + g;
#pragma unroll
        for (int ni = 0; ni < 4; ni++) {
            int p0 = wc2 * 32 + ni * 8 + 2 * q;
#pragma unroll
            for (int jj = 0; jj < 2; jj++) {
                int p = p0 + jj;
                float x0 = g_xc[(size_t)(t0 + t) * DCI + h * HD + p];
                float x1 = g_xc[(size_t)(t0 + t + 8) * DCI + h * HD + p];
                g_y[(size_t)(t0 + t) * DI + h * HD + p]     = acc2[mi][ni][jj]     + Dh * x0;
                g_y[(size_t)(t0 + t + 8) * DI + h * HD + p] = acc2[mi][ni][2 + jj] + Dh * x1;
            }
        }
    }
}

// ------------------------------ K4 -----------------------------------------
__global__ void k_norm(const float* __restrict__ nw, const float* __restrict__ nb) {
    int t = blockIdx.x, tid = threadIdx.x;
    __shared__ float red[256];
    float ss = 0.f;
    for (int i = tid; i < DI; i += 256) {
        float v = g_y[(size_t)t * DI + i];
        ss += v * v;
    }
    red[tid] = ss;
    __syncthreads();
    for (int o = 128; o > 0; o >>= 1) {
        if (tid < o) red[tid] += red[tid + o];
        __syncthreads();
    }
    float inv = rsqrtf(red[0] / (float)DI + 1e-6f);
    for (int i = tid; i < DI; i += 256) {
        float v = g_y[(size_t)t * DI + i] * inv * nw[i] + nb[i];
        float z = g_zx[(size_t)t * DIPP + i];
        float o = v * silu(z);
        split_store(&g_yg_hi[(size_t)t * DI + i], &g_yg_lo[(size_t)t * DI + i], o);
    }
}

// ------------------------------ host ----------------------------------------
extern "C" void kernel_launch(void* const* d_in, const int* in_sizes, int n_in,
                              void* d_out, int out_size) {
    const float* u       = (const float*)d_in[0];
    const float* W_in    = (const float*)d_in[1];
    const float* conv_w  = (const float*)d_in[2];
    const float* conv_b  = (const float*)d_in[3];
    const float* W_out   = (const float*)d_in[4];
    const float* norm_w  = (const float*)d_in[5];
    const float* norm_b  = (const float*)d_in[6];
    const float* dt_bias = (const float*)d_in[7];
    const float* A_log   = (const float*)d_in[8];
    const float* Dp      = (const float*)d_in[9];
    float* out = (float*)d_out;

    void *p_ub, *p_wih, *p_wil, *p_woh, *p_wol, *p_zx, *p_ygh, *p_ygl;
    cudaGetSymbolAddress(&p_ub, g_ub);
    cudaGetSymbolAddress(&p_wih, g_Win_hi);
    cudaGetSymbolAddress(&p_wil, g_Win_lo);
    cudaGetSymbolAddress(&p_woh, g_Wout_hi);
    cudaGetSymbolAddress(&p_wol, g_Wout_lo);
    cudaGetSymbolAddress(&p_zx, g_zx);
    cudaGetSymbolAddress(&p_ygh, g_yg_hi);
    cudaGetSymbolAddress(&p_ygl, g_yg_lo);

    const uint32_t smem0 = 3 * 3 * TILEB;   // 92160 (3 stages, 3 slots)
    const uint32_t smem1 = 2 * 4 * TILEB;   // 81920 (2 stages, 4 slots)
    cudaFuncSetAttribute((const void*)gemm_kernel<false, 3>,
                         cudaFuncAttributeMaxDynamicSharedMemorySize, smem0);
    cudaFuncSetAttribute((const void*)gemm_kernel<true, 2>,
                         cudaFuncAttributeMaxDynamicSharedMemorySize, smem1);
    cudaFuncSetAttribute((const void*)k_out,
                         cudaFuncAttributeMaxDynamicSharedMemorySize, KOUT_SMEM);

    k_cvt_u<<<4096, 256>>>(u);
    k_split_win<<<(DIPP * DM + 255) / 256, 256>>>(W_in);
    k_split_wout<<<(DM * DI + 255) / 256, 256>>>(W_out);

    gemm_kernel<false, 3><<<dim3(DIPP / 128, SEQ / 128), 256, smem0>>>(
        (const __nv_bfloat16*)p_ub, nullptr,
        (const __nv_bfloat16*)p_wih, (const __nv_bfloat16*)p_wil,
        (float*)p_zx, SEQ, DIPP, DM);

    k_conv<<<dim3(DCI / 256, SEQ / 64), 256>>>(conv_w, conv_b);
    k_dt<<<dim3(NC, NH), CH>>>(dt_bias, A_log);
    k_graw<<<NC, 256>>>();
    k_states<<<dim3(NC, NH), 256>>>();
    k_prop<<<(NH * HD * DS) / 256, 256>>>();
    k_out<<<dim3(NC, NH), 256, KOUT_SMEM>>>(Dp);
    k_norm<<<SEQ, 256>>>(norm_w, norm_b);

    gemm_kernel<true, 2><<<dim3(DM / 128, SEQ / 128), 256, smem1>>>(
        (const __nv_bfloat16*)p_ygh, (const __nv_bfloat16*)p_ygl,
        (const __nv_bfloat16*)p_woh, (const __nv_bfloat16*)p_wol,
        out, SEQ, DM, DI);
}